// round 5
// baseline (speedup 1.0000x reference)
#include <cuda_runtime.h>
#include <math.h>

#define B_ 2
#define CIN_ 8
#define H_ 224
#define W_ 224
#define F_ 64
#define E_ 8
#define P_ 10
#define S_ 5
#define K_ 7
#define N1_ 43
#define N_ 1849          // N1_*N1_
#define M_ 49            // (2*WIN+1)^2
#define D_ 800           // CIN_*P_*P_

// ---------------- scratch (static device globals; no allocation) ----------------
__device__ float g_t1e[B_*F_*H_*W_];
__device__ float g_t1t[B_*F_*H_*W_];
__device__ float g_t2e[B_*F_*H_*W_];
__device__ float g_t2t[B_*F_*H_*W_];
__device__ float g_xe[B_*E_*H_*W_];
__device__ float g_ltmap[B_*H_*W_];
__device__ float g_pe[B_*N_*D_];
__device__ float g_sq[B_*N_];
__device__ float g_ltm[B_*N_];
__device__ float g_nb[K_*B_*N_*D_];

// =================================================================
// conv1 fused: layer-1 of BOTH networks, shared input x (Cin=8), relu.
// block 256, tile 32x32, acc[4][16]: o<8 -> net A oc0+o, o>=8 -> net B.
// double-buffered smem staging.
// =================================================================
__global__ void __launch_bounds__(256, 2) conv1_fused(
    const float* __restrict__ x,
    const float* __restrict__ wA, const float* __restrict__ bA, float* __restrict__ outA,
    const float* __restrict__ wB, const float* __restrict__ bB, float* __restrict__ outB)
{
    __shared__ float s_in[2][34*34];
    __shared__ float s_w[2][144];
    int b   = blockIdx.z;
    int oc0 = blockIdx.y * 8;
    int tile = blockIdx.x;
    int tx = tile % 7, ty = tile / 7;
    int x0 = tx*32, y0 = ty*32;
    int tid = threadIdx.x;
    int lx = tid & 31, ly = tid >> 5;

    int goff[5];
    #pragma unroll
    for (int j=0;j<5;j++){
        int i = tid + j*256;
        goff[j] = -1;
        if (i < 34*34){
            int r = i/34, c = i%34;
            int gr = y0-1+r, gc = x0-1+c;
            goff[j] = (gr>=0 && gr<H_ && gc>=0 && gc<W_) ? gr*W_+gc : -1;
        }
    }
    const float* inbase = x + (size_t)b*CIN_*H_*W_;
    const float* wp = wA;
    if (tid < 144){
        int o = tid/9, kk = tid%9;
        wp = (o < 8) ? (wA + ((oc0+o)*CIN_)*9 + kk)
                     : (wB + ((oc0+o-8)*CIN_)*9 + kk);
    }

    // stage ic = 0
    {
        const float* inp = inbase;
        #pragma unroll
        for (int j=0;j<5;j++){
            int i = tid + j*256;
            if (i < 34*34) s_in[0][i] = (goff[j] >= 0) ? inp[goff[j]] : 0.f;
        }
        if (tid < 144) s_w[0][tid] = wp[0];
    }
    __syncthreads();

    float acc[4][16];
    #pragma unroll
    for (int p=0;p<4;p++)
        #pragma unroll
        for (int o=0;o<16;o++) acc[p][o]=0.f;

    for (int ic=0; ic<CIN_; ic++){
        int buf = ic & 1;
        if (ic+1 < CIN_){
            const float* inp = inbase + (size_t)(ic+1)*H_*W_;
            int nb = buf^1;
            #pragma unroll
            for (int j=0;j<5;j++){
                int i = tid + j*256;
                if (i < 34*34) s_in[nb][i] = (goff[j] >= 0) ? inp[goff[j]] : 0.f;
            }
            if (tid < 144) s_w[nb][tid] = wp[(ic+1)*9];
        }
        const float* si = s_in[buf];
        const float* sw = s_w[buf];
        #pragma unroll
        for (int dr=0;dr<3;dr++){
            #pragma unroll
            for (int dc=0;dc<3;dc++){
                int kk = dr*3+dc;
                float v0 = si[(ly   +dr)*34 + lx+dc];
                float v1 = si[(ly+ 8+dr)*34 + lx+dc];
                float v2 = si[(ly+16+dr)*34 + lx+dc];
                float v3 = si[(ly+24+dr)*34 + lx+dc];
                #pragma unroll
                for (int o=0;o<16;o++){
                    float wv = sw[o*9+kk];
                    acc[0][o] = fmaf(v0,wv,acc[0][o]);
                    acc[1][o] = fmaf(v1,wv,acc[1][o]);
                    acc[2][o] = fmaf(v2,wv,acc[2][o]);
                    acc[3][o] = fmaf(v3,wv,acc[3][o]);
                }
            }
        }
        __syncthreads();
    }

    #pragma unroll
    for (int o=0;o<16;o++){
        int oc = oc0 + ((o<8) ? o : o-8);
        float bv = (o<8) ? bA[oc] : bB[oc];
        float* op = (o<8) ? outA : outB;
        #pragma unroll
        for (int p=0;p<4;p++){
            float r = fmaxf(acc[p][o] + bv, 0.f);
            op[((size_t)(b*F_+oc)*H_ + (y0+ly+p*8))*W_ + x0+lx] = r;
        }
    }
}

// =================================================================
// conv2: 64->64, relu. blockIdx.y<4 -> net A group y, else net B.
// 16 oc per block, double-buffered smem.
// =================================================================
__global__ void __launch_bounds__(256, 2) conv64x64(
    const float* __restrict__ inA, const float* __restrict__ wA,
    const float* __restrict__ bA, float* __restrict__ outA,
    const float* __restrict__ inB, const float* __restrict__ wB,
    const float* __restrict__ bB, float* __restrict__ outB)
{
    __shared__ float s_in[2][34*34];
    __shared__ float s_w[2][144];
    int b = blockIdx.z;
    int g = blockIdx.y;
    const float* in; const float* wgt; const float* bias; float* out;
    if (g < 4){ in=inA; wgt=wA; bias=bA; out=outA; }
    else { g -= 4; in=inB; wgt=wB; bias=bB; out=outB; }
    int oc0 = g*16;

    int tile = blockIdx.x;
    int tx = tile % 7, ty = tile / 7;
    int x0 = tx*32, y0 = ty*32;
    int tid = threadIdx.x;
    int lx = tid & 31, ly = tid >> 5;

    int goff[5];
    #pragma unroll
    for (int j=0;j<5;j++){
        int i = tid + j*256;
        goff[j] = -1;
        if (i < 34*34){
            int r = i/34, c = i%34;
            int gr = y0-1+r, gc = x0-1+c;
            goff[j] = (gr>=0 && gr<H_ && gc>=0 && gc<W_) ? gr*W_+gc : -1;
        }
    }
    const float* inbase = in + (size_t)b*F_*H_*W_;
    const float* wp = wgt;
    if (tid < 144){
        int o = tid/9, kk = tid%9;
        wp = wgt + ((oc0+o)*F_)*9 + kk;
    }

    {
        const float* inp = inbase;
        #pragma unroll
        for (int j=0;j<5;j++){
            int i = tid + j*256;
            if (i < 34*34) s_in[0][i] = (goff[j] >= 0) ? inp[goff[j]] : 0.f;
        }
        if (tid < 144) s_w[0][tid] = wp[0];
    }
    __syncthreads();

    float acc[4][16];
    #pragma unroll
    for (int p=0;p<4;p++)
        #pragma unroll
        for (int o=0;o<16;o++) acc[p][o]=0.f;

    for (int ic=0; ic<F_; ic++){
        int buf = ic & 1;
        if (ic+1 < F_){
            const float* inp = inbase + (size_t)(ic+1)*H_*W_;
            int nb = buf^1;
            #pragma unroll
            for (int j=0;j<5;j++){
                int i = tid + j*256;
                if (i < 34*34) s_in[nb][i] = (goff[j] >= 0) ? inp[goff[j]] : 0.f;
            }
            if (tid < 144) s_w[nb][tid] = wp[(ic+1)*9];
        }
        const float* si = s_in[buf];
        const float* sw = s_w[buf];
        #pragma unroll
        for (int dr=0;dr<3;dr++){
            #pragma unroll
            for (int dc=0;dc<3;dc++){
                int kk = dr*3+dc;
                float v0 = si[(ly   +dr)*34 + lx+dc];
                float v1 = si[(ly+ 8+dr)*34 + lx+dc];
                float v2 = si[(ly+16+dr)*34 + lx+dc];
                float v3 = si[(ly+24+dr)*34 + lx+dc];
                #pragma unroll
                for (int o=0;o<16;o++){
                    float wv = sw[o*9+kk];
                    acc[0][o] = fmaf(v0,wv,acc[0][o]);
                    acc[1][o] = fmaf(v1,wv,acc[1][o]);
                    acc[2][o] = fmaf(v2,wv,acc[2][o]);
                    acc[3][o] = fmaf(v3,wv,acc[3][o]);
                }
            }
        }
        __syncthreads();
    }

    #pragma unroll
    for (int o=0;o<16;o++){
        int oc = oc0 + o;
        float bv = bias[oc];
        #pragma unroll
        for (int p=0;p<4;p++){
            float r = fmaxf(acc[p][o] + bv, 0.f);
            out[((size_t)(b*F_+oc)*H_ + (y0+ly+p*8))*W_ + x0+lx] = r;
        }
    }
}

// ---------------- generic dual-network 3x3 conv (layer 3 only) ----------------
__global__ void __launch_bounds__(256, 4) conv3x3_dual(
    const float* __restrict__ inA, const float* __restrict__ wA,
    const float* __restrict__ bA, float* __restrict__ outA, int CoutA,
    const float* __restrict__ inB, const float* __restrict__ wB,
    const float* __restrict__ bB, float* __restrict__ outB, int CoutB,
    int Cin, int relu, int gA)
{
    __shared__ float s_in[34][34];
    __shared__ float s_w[8][9];
    int b   = blockIdx.z;
    int ocg = blockIdx.y;
    const float* in; const float* wgt; const float* bias; float* out; int Cout;
    if (ocg < gA){ in=inA; wgt=wA; bias=bA; out=outA; Cout=CoutA; }
    else { ocg -= gA; in=inB; wgt=wB; bias=bB; out=outB; Cout=CoutB; }

    int tile = blockIdx.x;
    int tx = tile % 7, ty = tile / 7;
    int x0 = tx*32, y0 = ty*32;
    int lx = threadIdx.x, ly = threadIdx.y;
    int tid = ly*32 + lx;

    float acc[4][8];
    #pragma unroll
    for (int p=0;p<4;p++)
        #pragma unroll
        for (int o=0;o<8;o++) acc[p][o]=0.f;

    for (int ic=0; ic<Cin; ic++){
        const float* inp = in + ((size_t)(b*Cin + ic))*H_*W_;
        for (int i=tid; i<34*34; i+=256){
            int r = i/34, c = i%34;
            int gr = y0-1+r, gc = x0-1+c;
            float v = 0.f;
            if (gr>=0 && gr<H_ && gc>=0 && gc<W_) v = inp[gr*W_+gc];
            s_in[r][c] = v;
        }
        if (tid < 72){
            int o = tid/9, kk = tid%9;
            int oc = ocg*8+o;
            s_w[o][kk] = (oc<Cout) ? wgt[(oc*Cin+ic)*9 + kk] : 0.f;
        }
        __syncthreads();

        #pragma unroll
        for (int dr=0;dr<3;dr++){
            #pragma unroll
            for (int dc=0;dc<3;dc++){
                float v0 = s_in[ly     +dr][lx+dc];
                float v1 = s_in[ly+ 8  +dr][lx+dc];
                float v2 = s_in[ly+16  +dr][lx+dc];
                float v3 = s_in[ly+24  +dr][lx+dc];
                int kk = dr*3+dc;
                #pragma unroll
                for (int o=0;o<8;o++){
                    float wv = s_w[o][kk];
                    acc[0][o] = fmaf(v0, wv, acc[0][o]);
                    acc[1][o] = fmaf(v1, wv, acc[1][o]);
                    acc[2][o] = fmaf(v2, wv, acc[2][o]);
                    acc[3][o] = fmaf(v3, wv, acc[3][o]);
                }
            }
        }
        __syncthreads();
    }

    #pragma unroll
    for (int o=0;o<8;o++){
        int oc = ocg*8+o;
        if (oc<Cout){
            float bv = bias[oc];
            #pragma unroll
            for (int p=0;p<4;p++){
                float r = acc[p][o] + bv;
                if (relu) r = fmaxf(r, 0.f);
                out[((size_t)(b*Cout+oc)*H_ + (y0+ly+p*8))*W_ + x0+lx] = r;
            }
        }
    }
}

// ---------------- patch extraction: pe, ||pe||^2, mean log-temp ----------------
__global__ void patches_kernel()
{
    int bn = blockIdx.x;
    int b = bn / N_, n = bn % N_;
    int n1 = n / N1_, n2 = n % N1_;
    int r0 = n1*S_, c0 = n2*S_;
    int tid = threadIdx.x;   // 128

    float loc = 0.f;
    for (int d=tid; d<D_; d+=128){
        int c = d/100, rem = d%100, p1 = rem/10, p2 = rem%10;
        float v = g_xe[((b*E_+c)*H_ + r0+p1)*W_ + c0+p2];
        g_pe[(size_t)bn*D_ + d] = v;
        loc += v*v;
    }
    float lv = 0.f;
    if (tid < 100){
        int p1 = tid/10, p2 = tid%10;
        lv = g_ltmap[(b*H_ + r0+p1)*W_ + c0+p2];
    }
    __shared__ float r1s[4], r2s[4];
    int lane = tid & 31, wid = tid >> 5;
    #pragma unroll
    for (int off=16; off; off>>=1){
        loc += __shfl_xor_sync(0xffffffffu, loc, off);
        lv  += __shfl_xor_sync(0xffffffffu, lv,  off);
    }
    if (lane==0){ r1s[wid]=loc; r2s[wid]=lv; }
    __syncthreads();
    if (tid==0){
        g_sq[bn]  = r1s[0]+r1s[1]+r1s[2]+r1s[3];
        g_ltm[bn] = (r2s[0]+r2s[1]+r2s[2]+r2s[3]) * (1.f/100.f);
    }
}

// ------- fused: distances -> logits -> K iterative softmax -> aggregation -------
__global__ void __launch_bounds__(256) nnblock_kernel(const float* __restrict__ x)
{
    extern __shared__ float sm[];
    float* s_xf = sm;                 // 8 * 40 * 40 = 12800 floats
    float* s_q  = sm + 12800;         // 800 floats
    __shared__ float s_wk[M_][8];
    __shared__ float s_logit[M_];
    __shared__ int   s_cand[M_];
    __shared__ int   s_off[M_];

    int bn = blockIdx.x;
    int b = bn / N_, n = bn % N_;
    int q1 = n / N1_, q2 = n % N1_;
    int tid = threadIdx.x, lane = tid & 31, wid = tid >> 5;

    int c1lo = max(q1-3,0), c1hi = min(q1+3, N1_-1);
    int c2lo = max(q2-3,0), c2hi = min(q2+3, N1_-1);
    int rows = (c1hi-c1lo)*S_ + P_;
    int cols = (c2hi-c2lo)*S_ + P_;
    int r0 = c1lo*S_, c0 = c2lo*S_;

    if (tid < M_){
        int i = tid/7, j = tid%7;
        int c1 = min(max(q1+i-3,0), N1_-1);
        int c2 = min(max(q2+j-3,0), N1_-1);
        s_cand[tid] = c1*N1_ + c2;
        s_off[tid]  = ((c1-c1lo)*S_)*40 + (c2-c2lo)*S_;
    }
    for (int d=tid; d<D_; d+=256) s_q[d] = g_pe[(size_t)bn*D_ + d];

    #pragma unroll
    for (int c=0;c<CIN_;c++){
        const float* src = x + ((size_t)(b*CIN_+c)*H_ + r0)*W_ + c0;
        for (int r=wid; r<rows; r+=8)
            for (int cc=lane; cc<cols; cc+=32)
                s_xf[c*1600 + r*40 + cc] = src[r*W_ + cc];
    }
    __syncthreads();

    float sq_q  = g_sq[bn];
    float scale = expf(-g_ltm[bn]);

    for (int m=wid; m<M_; m+=8){
        int cand = s_cand[m];
        const float* pc = g_pe + (size_t)(b*N_+cand)*D_;
        float s = 0.f;
        for (int j=lane; j<D_; j+=32) s += s_q[j]*pc[j];
        #pragma unroll
        for (int off=16; off; off>>=1) s += __shfl_xor_sync(0xffffffffu, s, off);
        if (lane==0){
            float Dv = -(sq_q + g_sq[b*N_+cand] - 2.f*s);
            s_logit[m] = (cand==n) ? -1e9f : Dv*scale;
        }
    }
    __syncthreads();

    if (tid < 32){
        float a = s_logit[tid];
        bool hasb = (tid+32) < M_;
        float bvl = hasb ? s_logit[tid+32] : -INFINITY;
        #pragma unroll
        for (int k=0;k<K_;k++){
            float mx = fmaxf(a, bvl);
            #pragma unroll
            for (int off=16; off; off>>=1) mx = fmaxf(mx, __shfl_xor_sync(0xffffffffu, mx, off));
            float ea = expf(a - mx);
            float eb = hasb ? expf(bvl - mx) : 0.f;
            float ssum = ea + eb;
            #pragma unroll
            for (int off=16; off; off>>=1) ssum += __shfl_xor_sync(0xffffffffu, ssum, off);
            float inv = 1.f/ssum;
            float wa = ea*inv, wb = eb*inv;
            s_wk[tid][k] = wa;
            if (hasb) s_wk[tid+32][k] = wb;
            a   += log1pf(-fminf(wa, 1.f-1e-6f));
            bvl += log1pf(-fminf(wb, 1.f-1e-6f));
        }
    }
    __syncthreads();

    int baseidx[4]; bool act[4];
    #pragma unroll
    for (int j=0;j<4;j++){
        int d = tid + 256*j;
        act[j] = (d < D_);
        int dd = act[j] ? d : 0;
        int c = dd/100, rem = dd%100, p1 = rem/10, p2 = rem%10;
        baseidx[j] = c*1600 + p1*40 + p2;
    }
    float acc[4][K_];
    #pragma unroll
    for (int j=0;j<4;j++)
        #pragma unroll
        for (int k=0;k<K_;k++) acc[j][k]=0.f;

    for (int m=0;m<M_;m++){
        int o = s_off[m];
        float4 w0 = *(const float4*)&s_wk[m][0];
        float4 w1 = *(const float4*)&s_wk[m][4];
        float v[4];
        #pragma unroll
        for (int j=0;j<4;j++) v[j] = s_xf[baseidx[j]+o];
        #pragma unroll
        for (int j=0;j<4;j++){
            acc[j][0] = fmaf(w0.x, v[j], acc[j][0]);
            acc[j][1] = fmaf(w0.y, v[j], acc[j][1]);
            acc[j][2] = fmaf(w0.z, v[j], acc[j][2]);
            acc[j][3] = fmaf(w0.w, v[j], acc[j][3]);
            acc[j][4] = fmaf(w1.x, v[j], acc[j][4]);
            acc[j][5] = fmaf(w1.y, v[j], acc[j][5]);
            acc[j][6] = fmaf(w1.z, v[j], acc[j][6]);
        }
    }
    #pragma unroll
    for (int j=0;j<4;j++){
        if (!act[j]) continue;
        int d = tid + 256*j;
        #pragma unroll
        for (int k=0;k<K_;k++)
            g_nb[((size_t)(k*B_+b)*N_ + n)*D_ + d] = acc[j][k];
    }
}

// ---------------- gather fold + x passthrough + normalization ----------------
__global__ void fold_kernel(const float* __restrict__ x, float* __restrict__ out)
{
    int idx = blockIdx.x*blockDim.x + threadIdx.x;
    const int total = B_*(K_+1)*CIN_*H_*W_;
    if (idx >= total) return;
    int w  = idx % W_;
    int r  = (idx / W_) % H_;
    int ch = (idx / (H_*W_)) % ((K_+1)*CIN_);
    int b  = idx / (H_*W_*(K_+1)*CIN_);

    if (ch < CIN_){
        out[idx] = x[((b*CIN_+ch)*H_+r)*W_+w];
        return;
    }
    int k = (ch - CIN_) / CIN_;
    int c = (ch - CIN_) % CIN_;

    int n1lo = (r >= P_-1) ? (r-(P_-1)+S_-1)/S_ : 0;
    int n1hi = min(N1_-1, r/S_);
    int n2lo = (w >= P_-1) ? (w-(P_-1)+S_-1)/S_ : 0;
    int n2hi = min(N1_-1, w/S_);

    float sum = 0.f; int cnt = 0;
    for (int n1=n1lo; n1<=n1hi; n1++){
        int p1 = r - n1*S_;
        for (int n2=n2lo; n2<=n2hi; n2++){
            int p2 = w - n2*S_;
            sum += g_nb[((size_t)(k*B_+b)*N_ + n1*N1_+n2)*D_ + c*100 + p1*10 + p2];
            cnt++;
        }
    }
    out[idx] = (cnt > 0) ? sum/(float)cnt : 0.f;
}

// ---------------- launch ----------------
extern "C" void kernel_launch(void* const* d_in, const int* in_sizes, int n_in,
                              void* d_out, int out_size)
{
    const float* x   = (const float*)d_in[0];
    const float* w1e = (const float*)d_in[1];
    const float* b1e = (const float*)d_in[2];
    const float* w2e = (const float*)d_in[3];
    const float* b2e = (const float*)d_in[4];
    const float* w3e = (const float*)d_in[5];
    const float* b3e = (const float*)d_in[6];
    const float* w1t = (const float*)d_in[7];
    const float* b1t = (const float*)d_in[8];
    const float* w2t = (const float*)d_in[9];
    const float* b2t = (const float*)d_in[10];
    const float* w3t = (const float*)d_in[11];
    const float* b3t = (const float*)d_in[12];

    float *t1e, *t1t, *t2e, *t2t, *xe, *ltmap;
    cudaGetSymbolAddress((void**)&t1e,   g_t1e);
    cudaGetSymbolAddress((void**)&t1t,   g_t1t);
    cudaGetSymbolAddress((void**)&t2e,   g_t2e);
    cudaGetSymbolAddress((void**)&t2t,   g_t2t);
    cudaGetSymbolAddress((void**)&xe,    g_xe);
    cudaGetSymbolAddress((void**)&ltmap, g_ltmap);

    static int attr_done = 0;
    if (!attr_done){
        cudaFuncSetAttribute(nnblock_kernel,
                             cudaFuncAttributeMaxDynamicSharedMemorySize, 56*1024);
        attr_done = 1;
    }

    // layer 1: fused over both networks (shared input staging)
    conv1_fused<<<dim3(49,8,B_), 256>>>(x, w1e, b1e, t1e, w1t, b1t, t1t);
    // layer 2: specialized 64->64, 16 oc/block, double-buffered
    conv64x64<<<dim3(49,8,B_), 256>>>(t1e, w2e, b2e, t2e, t1t, w2t, b2t, t2t);
    // layer 3: 8-ch embedding + 1-ch log-temp
    conv3x3_dual<<<dim3(49,2,B_), dim3(32,8)>>>(t2e, w3e, b3e, xe,    E_,
                                                t2t, w3t, b3t, ltmap, 1, F_, 0, 1);

    patches_kernel<<<B_*N_, 128>>>();
    nnblock_kernel<<<B_*N_, 256, (12800+800)*sizeof(float)>>>(x);

    const int total = B_*(K_+1)*CIN_*H_*W_;
    fold_kernel<<<(total+255)/256, 256>>>(x, (float*)d_out);
}

// round 6
// speedup vs baseline: 1.2361x; 1.2361x over previous
#include <cuda_runtime.h>
#include <math.h>

#define B_ 2
#define CIN_ 8
#define H_ 224
#define W_ 224
#define F_ 64
#define E_ 8
#define P_ 10
#define S_ 5
#define K_ 7
#define N1_ 43
#define N_ 1849
#define M_ 49
#define D_ 800

typedef unsigned long long ull;
__device__ __forceinline__ void ffma2(ull &d, ull a, ull b){
    asm("fma.rn.f32x2 %0, %1, %2, %0;" : "+l"(d) : "l"(a), "l"(b));
}
__device__ __forceinline__ ull pack2s(float x){
    ull r; asm("mov.b64 %0, {%1, %1};" : "=l"(r) : "f"(x)); return r;
}
__device__ __forceinline__ void unpack2(float &x, float &y, ull v){
    asm("mov.b64 {%0, %1}, %2;" : "=f"(x), "=f"(y) : "l"(v));
}

// ---------------- scratch ----------------
__device__ float g_t1e[B_*F_*H_*W_];
__device__ float g_t1t[B_*F_*H_*W_];
__device__ float g_t2e[B_*F_*H_*W_];
__device__ float g_t2t[B_*F_*H_*W_];
__device__ float g_xe[B_*E_*H_*W_];
__device__ float g_ltmap[B_*H_*W_];
__device__ float g_pe[B_*N_*D_];
__device__ float g_sq[B_*N_];
__device__ float g_ltm[B_*N_];
__device__ float g_nb[K_*B_*N_*D_];

// ============ conv1 fused (both nets share staged x), FFMA2 ============
// s_w layout [kk][o] so o-pairs are contiguous for LDS.64
__global__ void __launch_bounds__(256, 2) conv1_fused(
    const float* __restrict__ x,
    const float* __restrict__ wA, const float* __restrict__ bA, float* __restrict__ outA,
    const float* __restrict__ wB, const float* __restrict__ bB, float* __restrict__ outB)
{
    __shared__ float s_in[2][34*34];
    __shared__ __align__(8) float s_w[2][9*16];
    int b = blockIdx.z, oc0 = blockIdx.y * 8;
    int tile = blockIdx.x, tx = tile % 7, ty = tile / 7;
    int x0 = tx*32, y0 = ty*32;
    int tid = threadIdx.x, lx = tid & 31, ly = tid >> 5;

    int goff[5];
    #pragma unroll
    for (int j=0;j<5;j++){
        int i = tid + j*256; goff[j] = -1;
        if (i < 34*34){
            int r = i/34, c = i%34, gr = y0-1+r, gc = x0-1+c;
            goff[j] = (gr>=0 && gr<H_ && gc>=0 && gc<W_) ? gr*W_+gc : -1;
        }
    }
    const float* inbase = x + (size_t)b*CIN_*H_*W_;
    const float* wp = wA; int wslot = 0;
    if (tid < 144){
        int o = tid/9, kk = tid%9;
        wslot = kk*16 + o;
        wp = (o < 8) ? (wA + ((oc0+o)*CIN_)*9 + kk)
                     : (wB + ((oc0+o-8)*CIN_)*9 + kk);
    }
    {
        #pragma unroll
        for (int j=0;j<5;j++){
            int i = tid + j*256;
            if (i < 34*34) s_in[0][i] = (goff[j] >= 0) ? inbase[goff[j]] : 0.f;
        }
        if (tid < 144) s_w[0][wslot] = wp[0];
    }
    __syncthreads();

    ull acc[4][8];
    #pragma unroll
    for (int p=0;p<4;p++)
        #pragma unroll
        for (int o=0;o<8;o++) acc[p][o]=0ull;

    for (int ic=0; ic<CIN_; ic++){
        int buf = ic & 1;
        if (ic+1 < CIN_){
            const float* inp = inbase + (size_t)(ic+1)*H_*W_;
            int nb = buf^1;
            #pragma unroll
            for (int j=0;j<5;j++){
                int i = tid + j*256;
                if (i < 34*34) s_in[nb][i] = (goff[j] >= 0) ? inp[goff[j]] : 0.f;
            }
            if (tid < 144) s_w[nb][wslot] = wp[(ic+1)*9];
        }
        const float* si = s_in[buf];
        #pragma unroll
        for (int dr=0;dr<3;dr++){
            #pragma unroll
            for (int dc=0;dc<3;dc++){
                int kk = dr*3+dc;
                ull v0 = pack2s(si[(ly   +dr)*34 + lx+dc]);
                ull v1 = pack2s(si[(ly+ 8+dr)*34 + lx+dc]);
                ull v2 = pack2s(si[(ly+16+dr)*34 + lx+dc]);
                ull v3 = pack2s(si[(ly+24+dr)*34 + lx+dc]);
                const ull* wrow = (const ull*)&s_w[buf][kk*16];
                #pragma unroll
                for (int op=0;op<8;op++){
                    ull w2 = wrow[op];
                    ffma2(acc[0][op], v0, w2);
                    ffma2(acc[1][op], v1, w2);
                    ffma2(acc[2][op], v2, w2);
                    ffma2(acc[3][op], v3, w2);
                }
            }
        }
        __syncthreads();
    }

    #pragma unroll
    for (int op=0;op<8;op++){
        #pragma unroll
        for (int h=0;h<2;h++){
            int o = op*2+h;
            int oc = oc0 + ((o<8) ? o : o-8);
            float bv = (o<8) ? bA[oc] : bB[oc];
            float* opt = (o<8) ? outA : outB;
            #pragma unroll
            for (int p=0;p<4;p++){
                float a0,a1; unpack2(a0,a1,acc[p][op]);
                float r = fmaxf((h ? a1 : a0) + bv, 0.f);
                opt[((size_t)(b*F_+oc)*H_ + (y0+ly+p*8))*W_ + x0+lx] = r;
            }
        }
    }
}

// ============ conv2 64->64 dual, FFMA2, 16 oc/block ============
__global__ void __launch_bounds__(256, 2) conv64x64(
    const float* __restrict__ inA, const float* __restrict__ wA,
    const float* __restrict__ bA, float* __restrict__ outA,
    const float* __restrict__ inB, const float* __restrict__ wB,
    const float* __restrict__ bB, float* __restrict__ outB)
{
    __shared__ float s_in[2][34*34];
    __shared__ __align__(8) float s_w[2][9*16];
    int b = blockIdx.z, g = blockIdx.y;
    const float* in; const float* wgt; const float* bias; float* out;
    if (g < 4){ in=inA; wgt=wA; bias=bA; out=outA; }
    else { g -= 4; in=inB; wgt=wB; bias=bB; out=outB; }
    int oc0 = g*16;

    int tile = blockIdx.x, tx = tile % 7, ty = tile / 7;
    int x0 = tx*32, y0 = ty*32;
    int tid = threadIdx.x, lx = tid & 31, ly = tid >> 5;

    int goff[5];
    #pragma unroll
    for (int j=0;j<5;j++){
        int i = tid + j*256; goff[j] = -1;
        if (i < 34*34){
            int r = i/34, c = i%34, gr = y0-1+r, gc = x0-1+c;
            goff[j] = (gr>=0 && gr<H_ && gc>=0 && gc<W_) ? gr*W_+gc : -1;
        }
    }
    const float* inbase = in + (size_t)b*F_*H_*W_;
    const float* wp = wgt; int wslot = 0;
    if (tid < 144){
        int o = tid/9, kk = tid%9;
        wslot = kk*16 + o;
        wp = wgt + ((oc0+o)*F_)*9 + kk;
    }
    {
        #pragma unroll
        for (int j=0;j<5;j++){
            int i = tid + j*256;
            if (i < 34*34) s_in[0][i] = (goff[j] >= 0) ? inbase[goff[j]] : 0.f;
        }
        if (tid < 144) s_w[0][wslot] = wp[0];
    }
    __syncthreads();

    ull acc[4][8];
    #pragma unroll
    for (int p=0;p<4;p++)
        #pragma unroll
        for (int o=0;o<8;o++) acc[p][o]=0ull;

    for (int ic=0; ic<F_; ic++){
        int buf = ic & 1;
        if (ic+1 < F_){
            const float* inp = inbase + (size_t)(ic+1)*H_*W_;
            int nb = buf^1;
            #pragma unroll
            for (int j=0;j<5;j++){
                int i = tid + j*256;
                if (i < 34*34) s_in[nb][i] = (goff[j] >= 0) ? inp[goff[j]] : 0.f;
            }
            if (tid < 144) s_w[nb][wslot] = wp[(ic+1)*9];
        }
        const float* si = s_in[buf];
        #pragma unroll
        for (int dr=0;dr<3;dr++){
            #pragma unroll
            for (int dc=0;dc<3;dc++){
                int kk = dr*3+dc;
                ull v0 = pack2s(si[(ly   +dr)*34 + lx+dc]);
                ull v1 = pack2s(si[(ly+ 8+dr)*34 + lx+dc]);
                ull v2 = pack2s(si[(ly+16+dr)*34 + lx+dc]);
                ull v3 = pack2s(si[(ly+24+dr)*34 + lx+dc]);
                const ull* wrow = (const ull*)&s_w[buf][kk*16];
                #pragma unroll
                for (int op=0;op<8;op++){
                    ull w2 = wrow[op];
                    ffma2(acc[0][op], v0, w2);
                    ffma2(acc[1][op], v1, w2);
                    ffma2(acc[2][op], v2, w2);
                    ffma2(acc[3][op], v3, w2);
                }
            }
        }
        __syncthreads();
    }

    #pragma unroll
    for (int op=0;op<8;op++){
        float bv0 = bias[oc0+op*2], bv1 = bias[oc0+op*2+1];
        #pragma unroll
        for (int p=0;p<4;p++){
            float a0,a1; unpack2(a0,a1,acc[p][op]);
            size_t row = (size_t)(y0+ly+p*8)*W_ + x0+lx;
            out[((size_t)(b*F_+oc0+op*2  ))*H_*W_ + row] = fmaxf(a0+bv0, 0.f);
            out[((size_t)(b*F_+oc0+op*2+1))*H_*W_ + row] = fmaxf(a1+bv1, 0.f);
        }
    }
}

// ---------------- generic dual 3x3 conv (layer 3 only) ----------------
__global__ void __launch_bounds__(256, 4) conv3x3_dual(
    const float* __restrict__ inA, const float* __restrict__ wA,
    const float* __restrict__ bA, float* __restrict__ outA, int CoutA,
    const float* __restrict__ inB, const float* __restrict__ wB,
    const float* __restrict__ bB, float* __restrict__ outB, int CoutB,
    int Cin, int relu, int gA)
{
    __shared__ float s_in[34][34];
    __shared__ float s_w[8][9];
    int b = blockIdx.z, ocg = blockIdx.y;
    const float* in; const float* wgt; const float* bias; float* out; int Cout;
    if (ocg < gA){ in=inA; wgt=wA; bias=bA; out=outA; Cout=CoutA; }
    else { ocg -= gA; in=inB; wgt=wB; bias=bB; out=outB; Cout=CoutB; }

    int tile = blockIdx.x, tx = tile % 7, ty = tile / 7;
    int x0 = tx*32, y0 = ty*32;
    int lx = threadIdx.x, ly = threadIdx.y;
    int tid = ly*32 + lx;

    float acc[4][8];
    #pragma unroll
    for (int p=0;p<4;p++)
        #pragma unroll
        for (int o=0;o<8;o++) acc[p][o]=0.f;

    for (int ic=0; ic<Cin; ic++){
        const float* inp = in + ((size_t)(b*Cin + ic))*H_*W_;
        for (int i=tid; i<34*34; i+=256){
            int r = i/34, c = i%34, gr = y0-1+r, gc = x0-1+c;
            float v = 0.f;
            if (gr>=0 && gr<H_ && gc>=0 && gc<W_) v = inp[gr*W_+gc];
            s_in[r][c] = v;
        }
        if (tid < 72){
            int o = tid/9, kk = tid%9;
            int oc = ocg*8+o;
            s_w[o][kk] = (oc<Cout) ? wgt[(oc*Cin+ic)*9 + kk] : 0.f;
        }
        __syncthreads();
        #pragma unroll
        for (int dr=0;dr<3;dr++){
            #pragma unroll
            for (int dc=0;dc<3;dc++){
                float v0 = s_in[ly   +dr][lx+dc];
                float v1 = s_in[ly+ 8+dr][lx+dc];
                float v2 = s_in[ly+16+dr][lx+dc];
                float v3 = s_in[ly+24+dr][lx+dc];
                int kk = dr*3+dc;
                #pragma unroll
                for (int o=0;o<8;o++){
                    float wv = s_w[o][kk];
                    acc[0][o] = fmaf(v0, wv, acc[0][o]);
                    acc[1][o] = fmaf(v1, wv, acc[1][o]);
                    acc[2][o] = fmaf(v2, wv, acc[2][o]);
                    acc[3][o] = fmaf(v3, wv, acc[3][o]);
                }
            }
        }
        __syncthreads();
    }

    #pragma unroll
    for (int o=0;o<8;o++){
        int oc = ocg*8+o;
        if (oc<Cout){
            float bv = bias[oc];
            #pragma unroll
            for (int p=0;p<4;p++){
                float r = acc[p][o] + bv;
                if (relu) r = fmaxf(r, 0.f);
                out[((size_t)(b*Cout+oc)*H_ + (y0+ly+p*8))*W_ + x0+lx] = r;
            }
        }
    }
}

// ---------------- patches ----------------
__global__ void patches_kernel()
{
    int bn = blockIdx.x;
    int b = bn / N_, n = bn % N_;
    int n1 = n / N1_, n2 = n % N1_;
    int r0 = n1*S_, c0 = n2*S_;
    int tid = threadIdx.x;

    float loc = 0.f;
    for (int d=tid; d<D_; d+=128){
        int c = d/100, rem = d%100, p1 = rem/10, p2 = rem%10;
        float v = g_xe[((b*E_+c)*H_ + r0+p1)*W_ + c0+p2];
        g_pe[(size_t)bn*D_ + d] = v;
        loc += v*v;
    }
    float lv = 0.f;
    if (tid < 100){
        int p1 = tid/10, p2 = tid%10;
        lv = g_ltmap[(b*H_ + r0+p1)*W_ + c0+p2];
    }
    __shared__ float r1s[4], r2s[4];
    int lane = tid & 31, wid = tid >> 5;
    #pragma unroll
    for (int off=16; off; off>>=1){
        loc += __shfl_xor_sync(0xffffffffu, loc, off);
        lv  += __shfl_xor_sync(0xffffffffu, lv,  off);
    }
    if (lane==0){ r1s[wid]=loc; r2s[wid]=lv; }
    __syncthreads();
    if (tid==0){
        g_sq[bn]  = r1s[0]+r1s[1]+r1s[2]+r1s[3];
        g_ltm[bn] = (r2s[0]+r2s[1]+r2s[2]+r2s[3]) * (1.f/100.f);
    }
}

// ------- nnblock: distances -> K softmax -> aggregation (FFMA2 over k) -------
__global__ void __launch_bounds__(256) nnblock_kernel(const float* __restrict__ x)
{
    extern __shared__ float sm[];
    float* s_xf = sm;
    float* s_q  = sm + 12800;
    __shared__ __align__(8) float s_wk[M_][8];
    __shared__ float s_logit[M_];
    __shared__ int   s_cand[M_];
    __shared__ int   s_off[M_];

    int bn = blockIdx.x;
    int b = bn / N_, n = bn % N_;
    int q1 = n / N1_, q2 = n % N1_;
    int tid = threadIdx.x, lane = tid & 31, wid = tid >> 5;

    int c1lo = max(q1-3,0), c1hi = min(q1+3, N1_-1);
    int c2lo = max(q2-3,0), c2hi = min(q2+3, N1_-1);
    int rows = (c1hi-c1lo)*S_ + P_;
    int cols = (c2hi-c2lo)*S_ + P_;
    int r0 = c1lo*S_, c0 = c2lo*S_;

    if (tid < M_){
        int i = tid/7, j = tid%7;
        int c1 = min(max(q1+i-3,0), N1_-1);
        int c2 = min(max(q2+j-3,0), N1_-1);
        s_cand[tid] = c1*N1_ + c2;
        s_off[tid]  = ((c1-c1lo)*S_)*40 + (c2-c2lo)*S_;
    }
    for (int d=tid; d<D_; d+=256) s_q[d] = g_pe[(size_t)bn*D_ + d];

    #pragma unroll
    for (int c=0;c<CIN_;c++){
        const float* src = x + ((size_t)(b*CIN_+c)*H_ + r0)*W_ + c0;
        for (int r=wid; r<rows; r+=8)
            for (int cc=lane; cc<cols; cc+=32)
                s_xf[c*1600 + r*40 + cc] = src[r*W_ + cc];
    }
    __syncthreads();

    float sq_q  = g_sq[bn];
    float scale = expf(-g_ltm[bn]);

    for (int m=wid; m<M_; m+=8){
        int cand = s_cand[m];
        const float* pc = g_pe + (size_t)(b*N_+cand)*D_;
        float s = 0.f;
        for (int j=lane; j<D_; j+=32) s += s_q[j]*pc[j];
        #pragma unroll
        for (int off=16; off; off>>=1) s += __shfl_xor_sync(0xffffffffu, s, off);
        if (lane==0){
            float Dv = -(sq_q + g_sq[b*N_+cand] - 2.f*s);
            s_logit[m] = (cand==n) ? -1e9f : Dv*scale;
        }
    }
    __syncthreads();

    if (tid < 32){
        float a = s_logit[tid];
        bool hasb = (tid+32) < M_;
        float bvl = hasb ? s_logit[tid+32] : -INFINITY;
        #pragma unroll
        for (int k=0;k<K_;k++){
            float mx = fmaxf(a, bvl);
            #pragma unroll
            for (int off=16; off; off>>=1) mx = fmaxf(mx, __shfl_xor_sync(0xffffffffu, mx, off));
            float ea = expf(a - mx);
            float eb = hasb ? expf(bvl - mx) : 0.f;
            float ssum = ea + eb;
            #pragma unroll
            for (int off=16; off; off>>=1) ssum += __shfl_xor_sync(0xffffffffu, ssum, off);
            float inv = 1.f/ssum;
            float wa = ea*inv, wb = eb*inv;
            s_wk[tid][k] = wa;
            if (hasb) s_wk[tid+32][k] = wb;
            a   += log1pf(-fminf(wa, 1.f-1e-6f));
            bvl += log1pf(-fminf(wb, 1.f-1e-6f));
        }
    }
    __syncthreads();

    int baseidx[4]; bool act[4];
    #pragma unroll
    for (int j=0;j<4;j++){
        int d = tid + 256*j;
        act[j] = (d < D_);
        int dd = act[j] ? d : 0;
        int c = dd/100, rem = dd%100, p1 = rem/10, p2 = rem%10;
        baseidx[j] = c*1600 + p1*40 + p2;
    }
    ull a01[4], a23[4], a45[4];
    float a6[4];
    #pragma unroll
    for (int j=0;j<4;j++){ a01[j]=0ull; a23[j]=0ull; a45[j]=0ull; a6[j]=0.f; }

    for (int m=0;m<M_;m++){
        int o = s_off[m];
        const ull* wr = (const ull*)&s_wk[m][0];
        ull w01 = wr[0], w23 = wr[1], w45 = wr[2];
        float w6 = s_wk[m][6];
        #pragma unroll
        for (int j=0;j<4;j++){
            float v = s_xf[baseidx[j]+o];
            ull vv = pack2s(v);
            ffma2(a01[j], vv, w01);
            ffma2(a23[j], vv, w23);
            ffma2(a45[j], vv, w45);
            a6[j] = fmaf(w6, v, a6[j]);
        }
    }
    #pragma unroll
    for (int j=0;j<4;j++){
        if (!act[j]) continue;
        int d = tid + 256*j;
        float o0,o1,o2,o3,o4,o5;
        unpack2(o0,o1,a01[j]); unpack2(o2,o3,a23[j]); unpack2(o4,o5,a45[j]);
        float vals[7] = {o0,o1,o2,o3,o4,o5,a6[j]};
        #pragma unroll
        for (int k=0;k<K_;k++)
            g_nb[((size_t)(k*B_+b)*N_ + n)*D_ + d] = vals[k];
    }
}

// ---------------- fold ----------------
__global__ void fold_kernel(const float* __restrict__ x, float* __restrict__ out)
{
    int idx = blockIdx.x*blockDim.x + threadIdx.x;
    const int total = B_*(K_+1)*CIN_*H_*W_;
    if (idx >= total) return;
    int w  = idx % W_;
    int r  = (idx / W_) % H_;
    int ch = (idx / (H_*W_)) % ((K_+1)*CIN_);
    int b  = idx / (H_*W_*(K_+1)*CIN_);

    if (ch < CIN_){
        out[idx] = x[((b*CIN_+ch)*H_+r)*W_+w];
        return;
    }
    int k = (ch - CIN_) / CIN_;
    int c = (ch - CIN_) % CIN_;

    int n1lo = (r >= P_-1) ? (r-(P_-1)+S_-1)/S_ : 0;
    int n1hi = min(N1_-1, r/S_);
    int n2lo = (w >= P_-1) ? (w-(P_-1)+S_-1)/S_ : 0;
    int n2hi = min(N1_-1, w/S_);

    float sum = 0.f; int cnt = 0;
    for (int n1=n1lo; n1<=n1hi; n1++){
        int p1 = r - n1*S_;
        for (int n2=n2lo; n2<=n2hi; n2++){
            int p2 = w - n2*S_;
            sum += g_nb[((size_t)(k*B_+b)*N_ + n1*N1_+n2)*D_ + c*100 + p1*10 + p2];
            cnt++;
        }
    }
    out[idx] = (cnt > 0) ? sum/(float)cnt : 0.f;
}

// ---------------- launch ----------------
extern "C" void kernel_launch(void* const* d_in, const int* in_sizes, int n_in,
                              void* d_out, int out_size)
{
    const float* x   = (const float*)d_in[0];
    const float* w1e = (const float*)d_in[1];
    const float* b1e = (const float*)d_in[2];
    const float* w2e = (const float*)d_in[3];
    const float* b2e = (const float*)d_in[4];
    const float* w3e = (const float*)d_in[5];
    const float* b3e = (const float*)d_in[6];
    const float* w1t = (const float*)d_in[7];
    const float* b1t = (const float*)d_in[8];
    const float* w2t = (const float*)d_in[9];
    const float* b2t = (const float*)d_in[10];
    const float* w3t = (const float*)d_in[11];
    const float* b3t = (const float*)d_in[12];

    float *t1e, *t1t, *t2e, *t2t, *xe, *ltmap;
    cudaGetSymbolAddress((void**)&t1e,   g_t1e);
    cudaGetSymbolAddress((void**)&t1t,   g_t1t);
    cudaGetSymbolAddress((void**)&t2e,   g_t2e);
    cudaGetSymbolAddress((void**)&t2t,   g_t2t);
    cudaGetSymbolAddress((void**)&xe,    g_xe);
    cudaGetSymbolAddress((void**)&ltmap, g_ltmap);

    static int attr_done = 0;
    if (!attr_done){
        cudaFuncSetAttribute(nnblock_kernel,
                             cudaFuncAttributeMaxDynamicSharedMemorySize, 56*1024);
        attr_done = 1;
    }

    conv1_fused<<<dim3(49,8,B_), 256>>>(x, w1e, b1e, t1e, w1t, b1t, t1t);
    conv64x64<<<dim3(49,8,B_), 256>>>(t1e, w2e, b2e, t2e, t1t, w2t, b2t, t2t);
    conv3x3_dual<<<dim3(49,2,B_), dim3(32,8)>>>(t2e, w3e, b3e, xe,    E_,
                                                t2t, w3t, b3t, ltmap, 1, F_, 0, 1);

    patches_kernel<<<B_*N_, 128>>>();
    nnblock_kernel<<<B_*N_, 256, (12800+800)*sizeof(float)>>>(x);

    const int total = B_*(K_+1)*CIN_*H_*W_;
    fold_kernel<<<(total+255)/256, 256>>>(x, (float*)d_out);
}

// round 7
// speedup vs baseline: 1.2810x; 1.0364x over previous
#include <cuda_runtime.h>
#include <math.h>

#define B_ 2
#define CIN_ 8
#define H_ 224
#define W_ 224
#define F_ 64
#define E_ 8
#define P_ 10
#define S_ 5
#define K_ 7
#define N1_ 43
#define N_ 1849
#define M_ 49
#define D_ 800

typedef unsigned long long ull;
__device__ __forceinline__ void ffma2(ull &d, ull a, ull b){
    asm("fma.rn.f32x2 %0, %1, %2, %0;" : "+l"(d) : "l"(a), "l"(b));
}
__device__ __forceinline__ ull pack2s(float x){
    ull r; asm("mov.b64 %0, {%1, %1};" : "=l"(r) : "f"(x)); return r;
}
__device__ __forceinline__ void unpack2(float &x, float &y, ull v){
    asm("mov.b64 {%0, %1}, %2;" : "=f"(x), "=f"(y) : "l"(v));
}

__device__ float g_t1e[B_*F_*H_*W_];
__device__ float g_t1t[B_*F_*H_*W_];
__device__ float g_t2e[B_*F_*H_*W_];
__device__ float g_t2t[B_*F_*H_*W_];
__device__ float g_xe[B_*E_*H_*W_];
__device__ float g_ltmap[B_*H_*W_];
__device__ float g_pe[B_*N_*D_];
__device__ float g_sq[B_*N_];
__device__ float g_ltm[B_*N_];
__device__ float g_nb[K_*B_*N_*D_];

// ============ conv1 fused (both nets share staged x), FFMA2 ============
__global__ void __launch_bounds__(256, 2) conv1_fused(
    const float* __restrict__ x,
    const float* __restrict__ wA, const float* __restrict__ bA, float* __restrict__ outA,
    const float* __restrict__ wB, const float* __restrict__ bB, float* __restrict__ outB)
{
    __shared__ float s_in[2][34*34];
    __shared__ __align__(8) float s_w[2][9*16];
    int b = blockIdx.z, oc0 = blockIdx.y * 8;
    int tile = blockIdx.x, tx = tile % 7, ty = tile / 7;
    int x0 = tx*32, y0 = ty*32;
    int tid = threadIdx.x, lx = tid & 31, ly = tid >> 5;

    int goff[5];
    #pragma unroll
    for (int j=0;j<5;j++){
        int i = tid + j*256; goff[j] = -1;
        if (i < 34*34){
            int r = i/34, c = i%34, gr = y0-1+r, gc = x0-1+c;
            goff[j] = (gr>=0 && gr<H_ && gc>=0 && gc<W_) ? gr*W_+gc : -1;
        }
    }
    const float* inbase = x + (size_t)b*CIN_*H_*W_;
    const float* wp = wA; int wslot = 0;
    if (tid < 144){
        int o = tid/9, kk = tid%9;
        wslot = kk*16 + o;
        wp = (o < 8) ? (wA + ((oc0+o)*CIN_)*9 + kk)
                     : (wB + ((oc0+o-8)*CIN_)*9 + kk);
    }
    {
        #pragma unroll
        for (int j=0;j<5;j++){
            int i = tid + j*256;
            if (i < 34*34) s_in[0][i] = (goff[j] >= 0) ? inbase[goff[j]] : 0.f;
        }
        if (tid < 144) s_w[0][wslot] = wp[0];
    }
    __syncthreads();

    ull acc[4][8];
    #pragma unroll
    for (int p=0;p<4;p++)
        #pragma unroll
        for (int o=0;o<8;o++) acc[p][o]=0ull;

    for (int ic=0; ic<CIN_; ic++){
        int buf = ic & 1;
        if (ic+1 < CIN_){
            const float* inp = inbase + (size_t)(ic+1)*H_*W_;
            int nb = buf^1;
            #pragma unroll
            for (int j=0;j<5;j++){
                int i = tid + j*256;
                if (i < 34*34) s_in[nb][i] = (goff[j] >= 0) ? inp[goff[j]] : 0.f;
            }
            if (tid < 144) s_w[nb][wslot] = wp[(ic+1)*9];
        }
        const float* si = s_in[buf];
        #pragma unroll
        for (int dr=0;dr<3;dr++){
            #pragma unroll
            for (int dc=0;dc<3;dc++){
                int kk = dr*3+dc;
                ull v0 = pack2s(si[(ly   +dr)*34 + lx+dc]);
                ull v1 = pack2s(si[(ly+ 8+dr)*34 + lx+dc]);
                ull v2 = pack2s(si[(ly+16+dr)*34 + lx+dc]);
                ull v3 = pack2s(si[(ly+24+dr)*34 + lx+dc]);
                const ull* wrow = (const ull*)&s_w[buf][kk*16];
                #pragma unroll
                for (int op=0;op<8;op++){
                    ull w2 = wrow[op];
                    ffma2(acc[0][op], v0, w2);
                    ffma2(acc[1][op], v1, w2);
                    ffma2(acc[2][op], v2, w2);
                    ffma2(acc[3][op], v3, w2);
                }
            }
        }
        __syncthreads();
    }

    #pragma unroll
    for (int op=0;op<8;op++){
        #pragma unroll
        for (int h=0;h<2;h++){
            int o = op*2+h;
            int oc = oc0 + ((o<8) ? o : o-8);
            float bv = (o<8) ? bA[oc] : bB[oc];
            float* opt = (o<8) ? outA : outB;
            #pragma unroll
            for (int p=0;p<4;p++){
                float a0,a1; unpack2(a0,a1,acc[p][op]);
                float r = fmaxf((h ? a1 : a0) + bv, 0.f);
                opt[((size_t)(b*F_+oc)*H_ + (y0+ly+p*8))*W_ + x0+lx] = r;
            }
        }
    }
}

// ============ conv2 64->64 dual, FFMA2, 16 oc/block ============
__global__ void __launch_bounds__(256, 2) conv64x64(
    const float* __restrict__ inA, const float* __restrict__ wA,
    const float* __restrict__ bA, float* __restrict__ outA,
    const float* __restrict__ inB, const float* __restrict__ wB,
    const float* __restrict__ bB, float* __restrict__ outB)
{
    __shared__ float s_in[2][34*34];
    __shared__ __align__(8) float s_w[2][9*16];
    int b = blockIdx.z, g = blockIdx.y;
    const float* in; const float* wgt; const float* bias; float* out;
    if (g < 4){ in=inA; wgt=wA; bias=bA; out=outA; }
    else { g -= 4; in=inB; wgt=wB; bias=bB; out=outB; }
    int oc0 = g*16;

    int tile = blockIdx.x, tx = tile % 7, ty = tile / 7;
    int x0 = tx*32, y0 = ty*32;
    int tid = threadIdx.x, lx = tid & 31, ly = tid >> 5;

    int goff[5];
    #pragma unroll
    for (int j=0;j<5;j++){
        int i = tid + j*256; goff[j] = -1;
        if (i < 34*34){
            int r = i/34, c = i%34, gr = y0-1+r, gc = x0-1+c;
            goff[j] = (gr>=0 && gr<H_ && gc>=0 && gc<W_) ? gr*W_+gc : -1;
        }
    }
    const float* inbase = in + (size_t)b*F_*H_*W_;
    const float* wp = wgt; int wslot = 0;
    if (tid < 144){
        int o = tid/9, kk = tid%9;
        wslot = kk*16 + o;
        wp = wgt + ((oc0+o)*F_)*9 + kk;
    }
    {
        #pragma unroll
        for (int j=0;j<5;j++){
            int i = tid + j*256;
            if (i < 34*34) s_in[0][i] = (goff[j] >= 0) ? inbase[goff[j]] : 0.f;
        }
        if (tid < 144) s_w[0][wslot] = wp[0];
    }
    __syncthreads();

    ull acc[4][8];
    #pragma unroll
    for (int p=0;p<4;p++)
        #pragma unroll
        for (int o=0;o<8;o++) acc[p][o]=0ull;

    for (int ic=0; ic<F_; ic++){
        int buf = ic & 1;
        if (ic+1 < F_){
            const float* inp = inbase + (size_t)(ic+1)*H_*W_;
            int nb = buf^1;
            #pragma unroll
            for (int j=0;j<5;j++){
                int i = tid + j*256;
                if (i < 34*34) s_in[nb][i] = (goff[j] >= 0) ? inp[goff[j]] : 0.f;
            }
            if (tid < 144) s_w[nb][wslot] = wp[(ic+1)*9];
        }
        const float* si = s_in[buf];
        #pragma unroll
        for (int dr=0;dr<3;dr++){
            #pragma unroll
            for (int dc=0;dc<3;dc++){
                int kk = dr*3+dc;
                ull v0 = pack2s(si[(ly   +dr)*34 + lx+dc]);
                ull v1 = pack2s(si[(ly+ 8+dr)*34 + lx+dc]);
                ull v2 = pack2s(si[(ly+16+dr)*34 + lx+dc]);
                ull v3 = pack2s(si[(ly+24+dr)*34 + lx+dc]);
                const ull* wrow = (const ull*)&s_w[buf][kk*16];
                #pragma unroll
                for (int op=0;op<8;op++){
                    ull w2 = wrow[op];
                    ffma2(acc[0][op], v0, w2);
                    ffma2(acc[1][op], v1, w2);
                    ffma2(acc[2][op], v2, w2);
                    ffma2(acc[3][op], v3, w2);
                }
            }
        }
        __syncthreads();
    }

    #pragma unroll
    for (int op=0;op<8;op++){
        float bv0 = bias[oc0+op*2], bv1 = bias[oc0+op*2+1];
        #pragma unroll
        for (int p=0;p<4;p++){
            float a0,a1; unpack2(a0,a1,acc[p][op]);
            size_t row = (size_t)(y0+ly+p*8)*W_ + x0+lx;
            out[((size_t)(b*F_+oc0+op*2  ))*H_*W_ + row] = fmaxf(a0+bv0, 0.f);
            out[((size_t)(b*F_+oc0+op*2+1))*H_*W_ + row] = fmaxf(a1+bv1, 0.f);
        }
    }
}

// ---------------- dual 3x3 conv (layer 3), FFMA2 ----------------
__global__ void __launch_bounds__(256, 4) conv3x3_dual(
    const float* __restrict__ inA, const float* __restrict__ wA,
    const float* __restrict__ bA, float* __restrict__ outA, int CoutA,
    const float* __restrict__ inB, const float* __restrict__ wB,
    const float* __restrict__ bB, float* __restrict__ outB, int CoutB,
    int Cin, int relu, int gA)
{
    __shared__ float s_in[34*34];
    __shared__ __align__(8) float s_w[9*8];
    int b = blockIdx.z, ocg = blockIdx.y;
    const float* in; const float* wgt; const float* bias; float* out; int Cout;
    if (ocg < gA){ in=inA; wgt=wA; bias=bA; out=outA; Cout=CoutA; }
    else { ocg -= gA; in=inB; wgt=wB; bias=bB; out=outB; Cout=CoutB; }

    int tile = blockIdx.x, tx = tile % 7, ty = tile / 7;
    int x0 = tx*32, y0 = ty*32;
    int tid = threadIdx.x, lx = tid & 31, ly = tid >> 5;

    ull acc[4][4];
    #pragma unroll
    for (int p=0;p<4;p++)
        #pragma unroll
        for (int o=0;o<4;o++) acc[p][o]=0ull;

    for (int ic=0; ic<Cin; ic++){
        const float* inp = in + ((size_t)(b*Cin + ic))*H_*W_;
        for (int i=tid; i<34*34; i+=256){
            int r = i/34, c = i%34, gr = y0-1+r, gc = x0-1+c;
            float v = 0.f;
            if (gr>=0 && gr<H_ && gc>=0 && gc<W_) v = inp[gr*W_+gc];
            s_in[i] = v;
        }
        if (tid < 72){
            int o = tid/9, kk = tid%9;
            int oc = ocg*8+o;
            s_w[kk*8+o] = (oc<Cout) ? wgt[(oc*Cin+ic)*9 + kk] : 0.f;
        }
        __syncthreads();
        #pragma unroll
        for (int dr=0;dr<3;dr++){
            #pragma unroll
            for (int dc=0;dc<3;dc++){
                int kk = dr*3+dc;
                ull v0 = pack2s(s_in[(ly   +dr)*34 + lx+dc]);
                ull v1 = pack2s(s_in[(ly+ 8+dr)*34 + lx+dc]);
                ull v2 = pack2s(s_in[(ly+16+dr)*34 + lx+dc]);
                ull v3 = pack2s(s_in[(ly+24+dr)*34 + lx+dc]);
                const ull* wrow = (const ull*)&s_w[kk*8];
                #pragma unroll
                for (int op=0;op<4;op++){
                    ull w2 = wrow[op];
                    ffma2(acc[0][op], v0, w2);
                    ffma2(acc[1][op], v1, w2);
                    ffma2(acc[2][op], v2, w2);
                    ffma2(acc[3][op], v3, w2);
                }
            }
        }
        __syncthreads();
    }

    #pragma unroll
    for (int op=0;op<4;op++){
        #pragma unroll
        for (int h=0;h<2;h++){
            int o = op*2+h;
            int oc = ocg*8+o;
            if (oc < Cout){
                float bv = bias[oc];
                #pragma unroll
                for (int p=0;p<4;p++){
                    float a0,a1; unpack2(a0,a1,acc[p][op]);
                    float r = (h ? a1 : a0) + bv;
                    if (relu) r = fmaxf(r, 0.f);
                    out[((size_t)(b*Cout+oc)*H_ + (y0+ly+p*8))*W_ + x0+lx] = r;
                }
            }
        }
    }
}

// ---------------- patches ----------------
__global__ void patches_kernel()
{
    int bn = blockIdx.x;
    int b = bn / N_, n = bn % N_;
    int n1 = n / N1_, n2 = n % N1_;
    int r0 = n1*S_, c0 = n2*S_;
    int tid = threadIdx.x;

    float loc = 0.f;
    for (int d=tid; d<D_; d+=128){
        int c = d/100, rem = d%100, p1 = rem/10, p2 = rem%10;
        float v = g_xe[((b*E_+c)*H_ + r0+p1)*W_ + c0+p2];
        g_pe[(size_t)bn*D_ + d] = v;
        loc += v*v;
    }
    float lv = 0.f;
    if (tid < 100){
        int p1 = tid/10, p2 = tid%10;
        lv = g_ltmap[(b*H_ + r0+p1)*W_ + c0+p2];
    }
    __shared__ float r1s[4], r2s[4];
    int lane = tid & 31, wid = tid >> 5;
    #pragma unroll
    for (int off=16; off; off>>=1){
        loc += __shfl_xor_sync(0xffffffffu, loc, off);
        lv  += __shfl_xor_sync(0xffffffffu, lv,  off);
    }
    if (lane==0){ r1s[wid]=loc; r2s[wid]=lv; }
    __syncthreads();
    if (tid==0){
        g_sq[bn]  = r1s[0]+r1s[1]+r1s[2]+r1s[3];
        g_ltm[bn] = (r2s[0]+r2s[1]+r2s[2]+r2s[3]) * (1.f/100.f);
    }
}

// ------- nnblock: vectorized distances -> K softmax -> FFMA2 aggregation -------
__global__ void __launch_bounds__(256) nnblock_kernel(const float* __restrict__ x)
{
    extern __shared__ float sm[];
    float* s_xf = sm;                 // 12800
    float* s_q  = sm + 12800;         // 800 (16B aligned)
    __shared__ __align__(8) float s_wk[M_][8];
    __shared__ float s_logit[M_];
    __shared__ int   s_cand[M_];
    __shared__ int   s_off[M_];

    int bn = blockIdx.x;
    int b = bn / N_, n = bn % N_;
    int q1 = n / N1_, q2 = n % N1_;
    int tid = threadIdx.x, lane = tid & 31, wid = tid >> 5;

    int c1lo = max(q1-3,0), c1hi = min(q1+3, N1_-1);
    int c2lo = max(q2-3,0), c2hi = min(q2+3, N1_-1);
    int rows = (c1hi-c1lo)*S_ + P_;
    int cols = (c2hi-c2lo)*S_ + P_;
    int r0 = c1lo*S_, c0 = c2lo*S_;

    if (tid < M_){
        int i = tid/7, j = tid%7;
        int c1 = min(max(q1+i-3,0), N1_-1);
        int c2 = min(max(q2+j-3,0), N1_-1);
        s_cand[tid] = c1*N1_ + c2;
        s_off[tid]  = ((c1-c1lo)*S_)*40 + (c2-c2lo)*S_;
    }
    // stage query patch as float4 (200 float4)
    if (tid < 200)
        ((float4*)s_q)[tid] = ((const float4*)(g_pe + (size_t)bn*D_))[tid];

    #pragma unroll
    for (int c=0;c<CIN_;c++){
        const float* src = x + ((size_t)(b*CIN_+c)*H_ + r0)*W_ + c0;
        for (int r=wid; r<rows; r+=8)
            for (int cc=lane; cc<cols; cc+=32)
                s_xf[c*1600 + r*40 + cc] = src[r*W_ + cc];
    }
    __syncthreads();

    float sq_q  = g_sq[bn];
    float scale = expf(-g_ltm[bn]);

    // distances, vectorized: 200 float4 per candidate, fully unrolled
    const float4* sq4 = (const float4*)s_q;
    for (int m=wid; m<M_; m+=8){
        int cand = s_cand[m];
        const float4* pc = (const float4*)(g_pe + (size_t)(b*N_+cand)*D_);
        float s0=0.f, s1=0.f, s2=0.f, s3=0.f;
        #pragma unroll
        for (int j=0;j<6;j++){
            float4 a = pc[lane + j*32];
            float4 q = sq4[lane + j*32];
            s0 = fmaf(a.x,q.x,s0); s1 = fmaf(a.y,q.y,s1);
            s2 = fmaf(a.z,q.z,s2); s3 = fmaf(a.w,q.w,s3);
        }
        if (lane < 8){
            float4 a = pc[192+lane];
            float4 q = sq4[192+lane];
            s0 = fmaf(a.x,q.x,s0); s1 = fmaf(a.y,q.y,s1);
            s2 = fmaf(a.z,q.z,s2); s3 = fmaf(a.w,q.w,s3);
        }
        float s = (s0+s1)+(s2+s3);
        #pragma unroll
        for (int off=16; off; off>>=1) s += __shfl_xor_sync(0xffffffffu, s, off);
        if (lane==0){
            float Dv = -(sq_q + g_sq[b*N_+cand] - 2.f*s);
            s_logit[m] = (cand==n) ? -1e9f : Dv*scale;
        }
    }
    __syncthreads();

    if (tid < 32){
        float a = s_logit[tid];
        bool hasb = (tid+32) < M_;
        float bvl = hasb ? s_logit[tid+32] : -INFINITY;
        #pragma unroll
        for (int k=0;k<K_;k++){
            float mx = fmaxf(a, bvl);
            #pragma unroll
            for (int off=16; off; off>>=1) mx = fmaxf(mx, __shfl_xor_sync(0xffffffffu, mx, off));
            float ea = expf(a - mx);
            float eb = hasb ? expf(bvl - mx) : 0.f;
            float ssum = ea + eb;
            #pragma unroll
            for (int off=16; off; off>>=1) ssum += __shfl_xor_sync(0xffffffffu, ssum, off);
            float inv = 1.f/ssum;
            float wa = ea*inv, wb = eb*inv;
            s_wk[tid][k] = wa;
            if (hasb) s_wk[tid+32][k] = wb;
            a   += log1pf(-fminf(wa, 1.f-1e-6f));
            bvl += log1pf(-fminf(wb, 1.f-1e-6f));
        }
    }
    __syncthreads();

    int baseidx[4]; bool act[4];
    #pragma unroll
    for (int j=0;j<4;j++){
        int d = tid + 256*j;
        act[j] = (d < D_);
        int dd = act[j] ? d : 0;
        int c = dd/100, rem = dd%100, p1 = rem/10, p2 = rem%10;
        baseidx[j] = c*1600 + p1*40 + p2;
    }
    ull a01[4], a23[4], a45[4];
    float a6[4];
    #pragma unroll
    for (int j=0;j<4;j++){ a01[j]=0ull; a23[j]=0ull; a45[j]=0ull; a6[j]=0.f; }

    for (int m=0;m<M_;m++){
        int o = s_off[m];
        const ull* wr = (const ull*)&s_wk[m][0];
        ull w01 = wr[0], w23 = wr[1], w45 = wr[2];
        float w6 = s_wk[m][6];
        #pragma unroll
        for (int j=0;j<4;j++){
            float v = s_xf[baseidx[j]+o];
            ull vv = pack2s(v);
            ffma2(a01[j], vv, w01);
            ffma2(a23[j], vv, w23);
            ffma2(a45[j], vv, w45);
            a6[j] = fmaf(w6, v, a6[j]);
        }
    }
    #pragma unroll
    for (int j=0;j<4;j++){
        if (!act[j]) continue;
        int d = tid + 256*j;
        float o0,o1,o2,o3,o4,o5;
        unpack2(o0,o1,a01[j]); unpack2(o2,o3,a23[j]); unpack2(o4,o5,a45[j]);
        float vals[7] = {o0,o1,o2,o3,o4,o5,a6[j]};
        #pragma unroll
        for (int k=0;k<K_;k++)
            g_nb[((size_t)(k*B_+b)*N_ + n)*D_ + d] = vals[k];
    }
}

// ---------------- fold ----------------
__global__ void fold_kernel(const float* __restrict__ x, float* __restrict__ out)
{
    int idx = blockIdx.x*blockDim.x + threadIdx.x;
    const int total = B_*(K_+1)*CIN_*H_*W_;
    if (idx >= total) return;
    int w  = idx % W_;
    int r  = (idx / W_) % H_;
    int ch = (idx / (H_*W_)) % ((K_+1)*CIN_);
    int b  = idx / (H_*W_*(K_+1)*CIN_);

    if (ch < CIN_){
        out[idx] = x[((b*CIN_+ch)*H_+r)*W_+w];
        return;
    }
    int k = (ch - CIN_) / CIN_;
    int c = (ch - CIN_) % CIN_;

    int n1lo = (r >= P_-1) ? (r-(P_-1)+S_-1)/S_ : 0;
    int n1hi = min(N1_-1, r/S_);
    int n2lo = (w >= P_-1) ? (w-(P_-1)+S_-1)/S_ : 0;
    int n2hi = min(N1_-1, w/S_);

    float sum = 0.f; int cnt = 0;
    for (int n1=n1lo; n1<=n1hi; n1++){
        int p1 = r - n1*S_;
        for (int n2=n2lo; n2<=n2hi; n2++){
            int p2 = w - n2*S_;
            sum += g_nb[((size_t)(k*B_+b)*N_ + n1*N1_+n2)*D_ + c*100 + p1*10 + p2];
            cnt++;
        }
    }
    out[idx] = (cnt > 0) ? sum/(float)cnt : 0.f;
}

// ---------------- launch ----------------
extern "C" void kernel_launch(void* const* d_in, const int* in_sizes, int n_in,
                              void* d_out, int out_size)
{
    const float* x   = (const float*)d_in[0];
    const float* w1e = (const float*)d_in[1];
    const float* b1e = (const float*)d_in[2];
    const float* w2e = (const float*)d_in[3];
    const float* b2e = (const float*)d_in[4];
    const float* w3e = (const float*)d_in[5];
    const float* b3e = (const float*)d_in[6];
    const float* w1t = (const float*)d_in[7];
    const float* b1t = (const float*)d_in[8];
    const float* w2t = (const float*)d_in[9];
    const float* b2t = (const float*)d_in[10];
    const float* w3t = (const float*)d_in[11];
    const float* b3t = (const float*)d_in[12];

    float *t1e, *t1t, *t2e, *t2t, *xe, *ltmap;
    cudaGetSymbolAddress((void**)&t1e,   g_t1e);
    cudaGetSymbolAddress((void**)&t1t,   g_t1t);
    cudaGetSymbolAddress((void**)&t2e,   g_t2e);
    cudaGetSymbolAddress((void**)&t2t,   g_t2t);
    cudaGetSymbolAddress((void**)&xe,    g_xe);
    cudaGetSymbolAddress((void**)&ltmap, g_ltmap);

    static int attr_done = 0;
    if (!attr_done){
        cudaFuncSetAttribute(nnblock_kernel,
                             cudaFuncAttributeMaxDynamicSharedMemorySize, 56*1024);
        attr_done = 1;
    }

    conv1_fused<<<dim3(49,8,B_), 256>>>(x, w1e, b1e, t1e, w1t, b1t, t1t);
    conv64x64<<<dim3(49,8,B_), 256>>>(t1e, w2e, b2e, t2e, t1t, w2t, b2t, t2t);
    conv3x3_dual<<<dim3(49,2,B_), 256>>>(t2e, w3e, b3e, xe,    E_,
                                         t2t, w3t, b3t, ltmap, 1, F_, 0, 1);

    patches_kernel<<<B_*N_, 128>>>();
    nnblock_kernel<<<B_*N_, 256, (12800+800)*sizeof(float)>>>(x);

    const int total = B_*(K_+1)*CIN_*H_*W_;
    fold_kernel<<<(total+255)/256, 256>>>(x, (float*)d_out);
}

// round 9
// speedup vs baseline: 1.4833x; 1.1579x over previous
#include <cuda_runtime.h>
#include <cuda_bf16.h>
#include <math.h>
#include <stdint.h>

#define B_ 2
#define CIN_ 8
#define H_ 224
#define W_ 224
#define F_ 64
#define E_ 8
#define P_ 10
#define S_ 5
#define K_ 7
#define N1_ 43
#define N_ 1849
#define M_ 49
#define D_ 800

typedef unsigned long long ull;
__device__ __forceinline__ void ffma2(ull &d, ull a, ull b){
    asm("fma.rn.f32x2 %0, %1, %2, %0;" : "+l"(d) : "l"(a), "l"(b));
}
__device__ __forceinline__ ull pack2s(float x){
    ull r; asm("mov.b64 %0, {%1, %1};" : "=l"(r) : "f"(x)); return r;
}
__device__ __forceinline__ void unpack2(float &x, float &y, ull v){
    asm("mov.b64 {%0, %1}, %2;" : "=f"(x), "=f"(y) : "l"(v));
}

__device__ float g_t1e[B_*F_*H_*W_];
__device__ float g_t1t[B_*F_*H_*W_];
__device__ float g_t2e[B_*F_*H_*W_];
__device__ float g_t2t[B_*F_*H_*W_];
__device__ float g_xe[B_*E_*H_*W_];
__device__ float g_ltmap[B_*H_*W_];
__device__ float g_pe[B_*N_*D_];
__device__ float g_sq[B_*N_];
__device__ float g_ltm[B_*N_];
__device__ float g_nb[K_*B_*N_*D_];
__device__ __nv_bfloat16 g_nhwc_hi[4*226*226*64];
__device__ __nv_bfloat16 g_nhwc_lo[4*226*226*64];
__device__ __nv_bfloat16 g_bt_hi[2*9*64*64];
__device__ __nv_bfloat16 g_bt_lo[2*9*64*64];

__device__ __forceinline__ uint32_t smem_u32(const void* p){
    uint32_t a;
    asm("{ .reg .u64 t; cvta.to.shared.u64 t, %1; cvt.u32.u64 %0, t; }" : "=r"(a) : "l"(p));
    return a;
}
__device__ __forceinline__ uint32_t lds32(uint32_t addr){
    uint32_t v;
    asm volatile("ld.shared.b32 %0, [%1];" : "=r"(v) : "r"(addr));
    return v;
}
__device__ __forceinline__ void sts32(uint32_t addr, uint32_t v){
    asm volatile("st.shared.b32 [%0], %1;" :: "r"(addr), "r"(v) : "memory");
}
__device__ __forceinline__ void mma_bf16(float* d, const uint32_t* a, uint32_t b0, uint32_t b1){
    asm volatile("mma.sync.aligned.m16n8k16.row.col.f32.bf16.bf16.f32 "
        "{%0,%1,%2,%3}, {%4,%5,%6,%7}, {%8,%9}, {%0,%1,%2,%3};"
        : "+f"(d[0]),"+f"(d[1]),"+f"(d[2]),"+f"(d[3])
        : "r"(a[0]),"r"(a[1]),"r"(a[2]),"r"(a[3]), "r"(b0),"r"(b1));
}

// smem layout for conv2_mma (stride 144B per 64-ic slot: 4 mod 32 words => conflict-free)
#define HALO_LO_OFF 25920            // 180*144
#define CW_OFF      51840            // 2*180*144
#define CW_LO_OFF   82944            // 576*144
#define CSM_TOT     217728           // 51840 + 2*576*144

// ---------- weight hi/lo table prep ----------
__global__ void wprep_kernel(const float* __restrict__ w2e, const float* __restrict__ w2t)
{
    int ns = blockIdx.x;
    int net = ns / 9, s = ns % 9;
    int dr = s / 3, dc = s % 3;
    const float* w = net ? w2t : w2e;
    int tid = threadIdx.x;
    for (int j = 0; j < 16; j++){
        int idx = tid + j*256;
        int oc = idx >> 6, ic = idx & 63;
        float v = w[((oc*64 + ic)*3 + dr)*3 + dc];
        __nv_bfloat16 hi = __float2bfloat16_rn(v);
        g_bt_hi[ns*4096 + idx] = hi;
        g_bt_lo[ns*4096 + idx] = __float2bfloat16_rn(v - __bfloat162float(hi));
    }
}

// ---------- t1 planar fp32 -> padded NHWC bf16 hi/lo ----------
__global__ void nhwc_convert(const float* __restrict__ t1e, const float* __restrict__ t1t)
{
    __shared__ float s[64][33];
    int bn = blockIdx.x;
    int b = bn >> 1, net = bn & 1;
    int rp = blockIdx.y;
    int cp0 = blockIdx.z * 32;
    int tid = threadIdx.x, lane = tid & 31, wid = tid >> 5;
    int r = rp - 1;
    const float* src = (net ? t1t : t1e) + (size_t)b*F_*H_*W_;

    for (int ic = wid; ic < 64; ic += 8){
        int c = cp0 + lane - 1;
        float v = 0.f;
        if (r >= 0 && r < H_ && c >= 0 && c < W_)
            v = src[(size_t)ic*H_*W_ + r*W_ + c];
        s[ic][lane] = v;
    }
    __syncthreads();

    uint32_t* hi_w = (uint32_t*)g_nhwc_hi;
    uint32_t* lo_w = (uint32_t*)g_nhwc_lo;
    for (int j = 0; j < 4; j++){
        int w = tid + j*256;
        int p = w >> 5, wl = w & 31;
        int cp = cp0 + p;
        if (cp >= 226) continue;
        float v0 = s[2*wl][p], v1 = s[2*wl+1][p];
        __nv_bfloat16 h0 = __float2bfloat16_rn(v0), h1 = __float2bfloat16_rn(v1);
        __nv_bfloat16 l0 = __float2bfloat16_rn(v0 - __bfloat162float(h0));
        __nv_bfloat16 l1 = __float2bfloat16_rn(v1 - __bfloat162float(h1));
        uint32_t hp = (uint32_t)__bfloat16_as_ushort(h0) | ((uint32_t)__bfloat16_as_ushort(h1) << 16);
        uint32_t lp = (uint32_t)__bfloat16_as_ushort(l0) | ((uint32_t)__bfloat16_as_ushort(l1) << 16);
        size_t wi = ((size_t)(bn*226 + rp)*226 + cp)*32 + wl;
        hi_w[wi] = hp;
        lo_w[wi] = lp;
    }
}

// ---------- conv2 via mma.sync m16n8k16 bf16 (3-term hi/lo split) ----------
// grid (392, 2, 2): tile = 8 rows x 16 cols; 8 warps = 8 pixel rows; N=64 oc.
__global__ void __launch_bounds__(256, 1)
conv2_mma(const float* __restrict__ b2e, const float* __restrict__ b2t)
{
    extern __shared__ char smem[];
    int bx = blockIdx.x;
    int net = blockIdx.y, b = blockIdx.z;
    int bn = b*2 + net;
    int ty = bx / 14, tx = bx % 14;
    int r0 = ty*8, c0 = tx*16;
    int tid = threadIdx.x, lane = tid & 31, w = tid >> 5;
    uint32_t smb = smem_u32(smem);

    // stage halo: 10 rows x 18 cols, hi + lo (slot = 64 ic = 32 words, stride 144B)
    const uint32_t* nh = (const uint32_t*)g_nhwc_hi;
    const uint32_t* nl = (const uint32_t*)g_nhwc_lo;
    for (int t = w; t < 360; t += 8){
        int arr = (t >= 180);
        int slot = arr ? t - 180 : t;
        int hr = slot / 18, hc = slot % 18;
        const uint32_t* src = (arr ? nl : nh) + ((size_t)(bn*226 + r0+hr)*226 + (c0+hc))*32;
        sts32(smb + (arr ? HALO_LO_OFF : 0) + slot*144 + lane*4, src[lane]);
    }
    // stage weights: 9 shifts x 64 oc rows (32 words each), hi + lo
    const uint32_t* bh = (const uint32_t*)g_bt_hi + net*18432/2*0 + (size_t)net*9*64*32;
    const uint32_t* bl = (const uint32_t*)g_bt_lo + (size_t)net*9*64*32;
    for (int t = w; t < 1152; t += 8){
        int arr = (t >= 576);
        int row = arr ? t - 576 : t;
        uint32_t v = (arr ? bl : bh)[row*32 + lane];
        sts32(smb + CW_OFF + (arr ? CW_LO_OFF : 0) + row*144 + lane*4, v);
    }
    __syncthreads();

    float acc[8][4];
    #pragma unroll
    for (int nt=0;nt<8;nt++)
        #pragma unroll
        for (int i=0;i<4;i++) acc[nt][i]=0.f;

    // per-thread invariant bases
    uint32_t aoff = smb + (uint32_t)(w*18 + (lane>>2))*144 + (lane&3)*4;
    uint32_t boff = smb + CW_OFF + (uint32_t)(lane>>2)*144 + (lane&3)*4;

    for (int s = 0; s < 9; s++){
        int dr = s/3, dc = s%3;
        uint32_t abase = aoff + (uint32_t)(dr*18 + dc)*144;
        uint32_t wbase = boff + (uint32_t)s*9216;          // s*64*144
        #pragma unroll
        for (int ks = 0; ks < 4; ks++){
            uint32_t ak = abase + ks*32;
            uint32_t ah[4], al[4];
            ah[0] = lds32(ak);
            ah[1] = lds32(ak + 1152);        // +8 pixels
            ah[2] = lds32(ak + 16);          // +8 k
            ah[3] = lds32(ak + 1168);
            al[0] = lds32(ak + HALO_LO_OFF);
            al[1] = lds32(ak + HALO_LO_OFF + 1152);
            al[2] = lds32(ak + HALO_LO_OFF + 16);
            al[3] = lds32(ak + HALO_LO_OFF + 1168);
            #pragma unroll
            for (int nt = 0; nt < 8; nt++){
                uint32_t bk = wbase + (uint32_t)nt*1152 + ks*32;
                uint32_t bh0 = lds32(bk);
                uint32_t bh1 = lds32(bk + 16);
                uint32_t bl0 = lds32(bk + CW_LO_OFF);
                uint32_t bl1 = lds32(bk + CW_LO_OFF + 16);
                mma_bf16(acc[nt], ah, bh0, bh1);   // hi*hi
                mma_bf16(acc[nt], ah, bl0, bl1);   // hi*lo
                mma_bf16(acc[nt], al, bh0, bh1);   // lo*hi
            }
        }
    }

    // epilogue: D rows = pixels, cols = oc
    const float* bias = net ? b2t : b2e;
    float* outp = (net ? g_t2t : g_t2e) + (size_t)b*F_*H_*W_;
    int orow = r0 + w;
    int pc = lane >> 2;
    int oc_b = (lane & 3) * 2;
    #pragma unroll
    for (int nt = 0; nt < 8; nt++){
        int oc = nt*8 + oc_b;
        float bv0 = bias[oc], bv1 = bias[oc+1];
        size_t base0 = (size_t)oc*(H_*W_) + (size_t)orow*W_ + c0;
        outp[base0 + pc]               = fmaxf(acc[nt][0] + bv0, 0.f);
        outp[base0 + H_*W_ + pc]       = fmaxf(acc[nt][1] + bv1, 0.f);
        outp[base0 + pc + 8]           = fmaxf(acc[nt][2] + bv0, 0.f);
        outp[base0 + H_*W_ + pc + 8]   = fmaxf(acc[nt][3] + bv1, 0.f);
    }
}

// ============ conv1 fused (FFMA2) ============
__global__ void __launch_bounds__(256, 2) conv1_fused(
    const float* __restrict__ x,
    const float* __restrict__ wA, const float* __restrict__ bA, float* __restrict__ outA,
    const float* __restrict__ wB, const float* __restrict__ bB, float* __restrict__ outB)
{
    __shared__ float s_in[2][34*34];
    __shared__ __align__(8) float s_w[2][9*16];
    int b = blockIdx.z, oc0 = blockIdx.y * 8;
    int tile = blockIdx.x, tx = tile % 7, ty = tile / 7;
    int x0 = tx*32, y0 = ty*32;
    int tid = threadIdx.x, lx = tid & 31, ly = tid >> 5;

    int goff[5];
    #pragma unroll
    for (int j=0;j<5;j++){
        int i = tid + j*256; goff[j] = -1;
        if (i < 34*34){
            int r = i/34, c = i%34, gr = y0-1+r, gc = x0-1+c;
            goff[j] = (gr>=0 && gr<H_ && gc>=0 && gc<W_) ? gr*W_+gc : -1;
        }
    }
    const float* inbase = x + (size_t)b*CIN_*H_*W_;
    const float* wp = wA; int wslot = 0;
    if (tid < 144){
        int o = tid/9, kk = tid%9;
        wslot = kk*16 + o;
        wp = (o < 8) ? (wA + ((oc0+o)*CIN_)*9 + kk)
                     : (wB + ((oc0+o-8)*CIN_)*9 + kk);
    }
    {
        #pragma unroll
        for (int j=0;j<5;j++){
            int i = tid + j*256;
            if (i < 34*34) s_in[0][i] = (goff[j] >= 0) ? inbase[goff[j]] : 0.f;
        }
        if (tid < 144) s_w[0][wslot] = wp[0];
    }
    __syncthreads();

    ull acc[4][8];
    #pragma unroll
    for (int p=0;p<4;p++)
        #pragma unroll
        for (int o=0;o<8;o++) acc[p][o]=0ull;

    for (int ic=0; ic<CIN_; ic++){
        int buf = ic & 1;
        if (ic+1 < CIN_){
            const float* inp = inbase + (size_t)(ic+1)*H_*W_;
            int nb = buf^1;
            #pragma unroll
            for (int j=0;j<5;j++){
                int i = tid + j*256;
                if (i < 34*34) s_in[nb][i] = (goff[j] >= 0) ? inp[goff[j]] : 0.f;
            }
            if (tid < 144) s_w[nb][wslot] = wp[(ic+1)*9];
        }
        const float* si = s_in[buf];
        #pragma unroll
        for (int dr=0;dr<3;dr++){
            #pragma unroll
            for (int dc=0;dc<3;dc++){
                int kk = dr*3+dc;
                ull v0 = pack2s(si[(ly   +dr)*34 + lx+dc]);
                ull v1 = pack2s(si[(ly+ 8+dr)*34 + lx+dc]);
                ull v2 = pack2s(si[(ly+16+dr)*34 + lx+dc]);
                ull v3 = pack2s(si[(ly+24+dr)*34 + lx+dc]);
                const ull* wrow = (const ull*)&s_w[buf][kk*16];
                #pragma unroll
                for (int op=0;op<8;op++){
                    ull w2 = wrow[op];
                    ffma2(acc[0][op], v0, w2);
                    ffma2(acc[1][op], v1, w2);
                    ffma2(acc[2][op], v2, w2);
                    ffma2(acc[3][op], v3, w2);
                }
            }
        }
        __syncthreads();
    }

    #pragma unroll
    for (int op=0;op<8;op++){
        #pragma unroll
        for (int h=0;h<2;h++){
            int o = op*2+h;
            int oc = oc0 + ((o<8) ? o : o-8);
            float bv = (o<8) ? bA[oc] : bB[oc];
            float* opt = (o<8) ? outA : outB;
            #pragma unroll
            for (int p=0;p<4;p++){
                float a0,a1; unpack2(a0,a1,acc[p][op]);
                float r = fmaxf((h ? a1 : a0) + bv, 0.f);
                opt[((size_t)(b*F_+oc)*H_ + (y0+ly+p*8))*W_ + x0+lx] = r;
            }
        }
    }
}

// ---------------- dual 3x3 conv (layer 3), FFMA2 ----------------
__global__ void __launch_bounds__(256, 4) conv3x3_dual(
    const float* __restrict__ inA, const float* __restrict__ wA,
    const float* __restrict__ bA, float* __restrict__ outA, int CoutA,
    const float* __restrict__ inB, const float* __restrict__ wB,
    const float* __restrict__ bB, float* __restrict__ outB, int CoutB,
    int Cin, int relu, int gA)
{
    __shared__ float s_in[34*34];
    __shared__ __align__(8) float s_w[9*8];
    int b = blockIdx.z, ocg = blockIdx.y;
    const float* in; const float* wgt; const float* bias; float* out; int Cout;
    if (ocg < gA){ in=inA; wgt=wA; bias=bA; out=outA; Cout=CoutA; }
    else { ocg -= gA; in=inB; wgt=wB; bias=bB; out=outB; Cout=CoutB; }

    int tile = blockIdx.x, tx = tile % 7, ty = tile / 7;
    int x0 = tx*32, y0 = ty*32;
    int tid = threadIdx.x, lx = tid & 31, ly = tid >> 5;

    ull acc[4][4];
    #pragma unroll
    for (int p=0;p<4;p++)
        #pragma unroll
        for (int o=0;o<4;o++) acc[p][o]=0ull;

    for (int ic=0; ic<Cin; ic++){
        const float* inp = in + ((size_t)(b*Cin + ic))*H_*W_;
        for (int i=tid; i<34*34; i+=256){
            int r = i/34, c = i%34, gr = y0-1+r, gc = x0-1+c;
            float v = 0.f;
            if (gr>=0 && gr<H_ && gc>=0 && gc<W_) v = inp[gr*W_+gc];
            s_in[i] = v;
        }
        if (tid < 72){
            int o = tid/9, kk = tid%9;
            int oc = ocg*8+o;
            s_w[kk*8+o] = (oc<Cout) ? wgt[(oc*Cin+ic)*9 + kk] : 0.f;
        }
        __syncthreads();
        #pragma unroll
        for (int dr=0;dr<3;dr++){
            #pragma unroll
            for (int dc=0;dc<3;dc++){
                int kk = dr*3+dc;
                ull v0 = pack2s(s_in[(ly   +dr)*34 + lx+dc]);
                ull v1 = pack2s(s_in[(ly+ 8+dr)*34 + lx+dc]);
                ull v2 = pack2s(s_in[(ly+16+dr)*34 + lx+dc]);
                ull v3 = pack2s(s_in[(ly+24+dr)*34 + lx+dc]);
                const ull* wrow = (const ull*)&s_w[kk*8];
                #pragma unroll
                for (int op=0;op<4;op++){
                    ull w2 = wrow[op];
                    ffma2(acc[0][op], v0, w2);
                    ffma2(acc[1][op], v1, w2);
                    ffma2(acc[2][op], v2, w2);
                    ffma2(acc[3][op], v3, w2);
                }
            }
        }
        __syncthreads();
    }

    #pragma unroll
    for (int op=0;op<4;op++){
        #pragma unroll
        for (int h=0;h<2;h++){
            int o = op*2+h;
            int oc = ocg*8+o;
            if (oc < Cout){
                float bv = bias[oc];
                #pragma unroll
                for (int p=0;p<4;p++){
                    float a0,a1; unpack2(a0,a1,acc[p][op]);
                    float r = (h ? a1 : a0) + bv;
                    if (relu) r = fmaxf(r, 0.f);
                    out[((size_t)(b*Cout+oc)*H_ + (y0+ly+p*8))*W_ + x0+lx] = r;
                }
            }
        }
    }
}

// ---------------- patches ----------------
__global__ void patches_kernel()
{
    int bn = blockIdx.x;
    int b = bn / N_, n = bn % N_;
    int n1 = n / N1_, n2 = n % N1_;
    int r0 = n1*S_, c0 = n2*S_;
    int tid = threadIdx.x;

    float loc = 0.f;
    for (int d=tid; d<D_; d+=128){
        int c = d/100, rem = d%100, p1 = rem/10, p2 = rem%10;
        float v = g_xe[((b*E_+c)*H_ + r0+p1)*W_ + c0+p2];
        g_pe[(size_t)bn*D_ + d] = v;
        loc += v*v;
    }
    float lv = 0.f;
    if (tid < 100){
        int p1 = tid/10, p2 = tid%10;
        lv = g_ltmap[(b*H_ + r0+p1)*W_ + c0+p2];
    }
    __shared__ float r1s[4], r2s[4];
    int lane = tid & 31, wid = tid >> 5;
    #pragma unroll
    for (int off=16; off; off>>=1){
        loc += __shfl_xor_sync(0xffffffffu, loc, off);
        lv  += __shfl_xor_sync(0xffffffffu, lv,  off);
    }
    if (lane==0){ r1s[wid]=loc; r2s[wid]=lv; }
    __syncthreads();
    if (tid==0){
        g_sq[bn]  = r1s[0]+r1s[1]+r1s[2]+r1s[3];
        g_ltm[bn] = (r2s[0]+r2s[1]+r2s[2]+r2s[3]) * (1.f/100.f);
    }
}

// ------- nnblock -------
__global__ void __launch_bounds__(256) nnblock_kernel(const float* __restrict__ x)
{
    extern __shared__ float sm[];
    float* s_xf = sm;
    float* s_q  = sm + 12800;
    __shared__ __align__(8) float s_wk[M_][8];
    __shared__ float s_logit[M_];
    __shared__ int   s_cand[M_];
    __shared__ int   s_off[M_];

    int bn = blockIdx.x;
    int b = bn / N_, n = bn % N_;
    int q1 = n / N1_, q2 = n % N1_;
    int tid = threadIdx.x, lane = tid & 31, wid = tid >> 5;

    int c1lo = max(q1-3,0), c1hi = min(q1+3, N1_-1);
    int c2lo = max(q2-3,0), c2hi = min(q2+3, N1_-1);
    int rows = (c1hi-c1lo)*S_ + P_;
    int cols = (c2hi-c2lo)*S_ + P_;
    int r0 = c1lo*S_, c0 = c2lo*S_;

    if (tid < M_){
        int i = tid/7, j = tid%7;
        int c1 = min(max(q1+i-3,0), N1_-1);
        int c2 = min(max(q2+j-3,0), N1_-1);
        s_cand[tid] = c1*N1_ + c2;
        s_off[tid]  = ((c1-c1lo)*S_)*40 + (c2-c2lo)*S_;
    }
    if (tid < 200)
        ((float4*)s_q)[tid] = ((const float4*)(g_pe + (size_t)bn*D_))[tid];

    #pragma unroll
    for (int c=0;c<CIN_;c++){
        const float* src = x + ((size_t)(b*CIN_+c)*H_ + r0)*W_ + c0;
        for (int r=wid; r<rows; r+=8)
            for (int cc=lane; cc<cols; cc+=32)
                s_xf[c*1600 + r*40 + cc] = src[r*W_ + cc];
    }
    __syncthreads();

    float sq_q  = g_sq[bn];
    float scale = expf(-g_ltm[bn]);

    const float4* sq4 = (const float4*)s_q;
    for (int m=wid; m<M_; m+=8){
        int cand = s_cand[m];
        const float4* pc = (const float4*)(g_pe + (size_t)(b*N_+cand)*D_);
        float s0=0.f, s1=0.f, s2=0.f, s3=0.f;
        #pragma unroll
        for (int j=0;j<6;j++){
            float4 a = pc[lane + j*32];
            float4 q = sq4[lane + j*32];
            s0 = fmaf(a.x,q.x,s0); s1 = fmaf(a.y,q.y,s1);
            s2 = fmaf(a.z,q.z,s2); s3 = fmaf(a.w,q.w,s3);
        }
        if (lane < 8){
            float4 a = pc[192+lane];
            float4 q = sq4[192+lane];
            s0 = fmaf(a.x,q.x,s0); s1 = fmaf(a.y,q.y,s1);
            s2 = fmaf(a.z,q.z,s2); s3 = fmaf(a.w,q.w,s3);
        }
        float s = (s0+s1)+(s2+s3);
        #pragma unroll
        for (int off=16; off; off>>=1) s += __shfl_xor_sync(0xffffffffu, s, off);
        if (lane==0){
            float Dv = -(sq_q + g_sq[b*N_+cand] - 2.f*s);
            s_logit[m] = (cand==n) ? -1e9f : Dv*scale;
        }
    }
    __syncthreads();

    if (tid < 32){
        float a = s_logit[tid];
        bool hasb = (tid+32) < M_;
        float bvl = hasb ? s_logit[tid+32] : -INFINITY;
        #pragma unroll
        for (int k=0;k<K_;k++){
            float mx = fmaxf(a, bvl);
            #pragma unroll
            for (int off=16; off; off>>=1) mx = fmaxf(mx, __shfl_xor_sync(0xffffffffu, mx, off));
            float ea = expf(a - mx);
            float eb = hasb ? expf(bvl - mx) : 0.f;
            float ssum = ea + eb;
            #pragma unroll
            for (int off=16; off; off>>=1) ssum += __shfl_xor_sync(0xffffffffu, ssum, off);
            float inv = 1.f/ssum;
            float wa = ea*inv, wb = eb*inv;
            s_wk[tid][k] = wa;
            if (hasb) s_wk[tid+32][k] = wb;
            a   += log1pf(-fminf(wa, 1.f-1e-6f));
            bvl += log1pf(-fminf(wb, 1.f-1e-6f));
        }
    }
    __syncthreads();

    int baseidx[4]; bool act[4];
    #pragma unroll
    for (int j=0;j<4;j++){
        int d = tid + 256*j;
        act[j] = (d < D_);
        int dd = act[j] ? d : 0;
        int c = dd/100, rem = dd%100, p1 = rem/10, p2 = rem%10;
        baseidx[j] = c*1600 + p1*40 + p2;
    }
    ull a01[4], a23[4], a45[4];
    float a6[4];
    #pragma unroll
    for (int j=0;j<4;j++){ a01[j]=0ull; a23[j]=0ull; a45[j]=0ull; a6[j]=0.f; }

    for (int m=0;m<M_;m++){
        int o = s_off[m];
        const ull* wr = (const ull*)&s_wk[m][0];
        ull w01 = wr[0], w23 = wr[1], w45 = wr[2];
        float w6 = s_wk[m][6];
        #pragma unroll
        for (int j=0;j<4;j++){
            float v = s_xf[baseidx[j]+o];
            ull vv = pack2s(v);
            ffma2(a01[j], vv, w01);
            ffma2(a23[j], vv, w23);
            ffma2(a45[j], vv, w45);
            a6[j] = fmaf(w6, v, a6[j]);
        }
    }
    #pragma unroll
    for (int j=0;j<4;j++){
        if (!act[j]) continue;
        int d = tid + 256*j;
        float o0,o1,o2,o3,o4,o5;
        unpack2(o0,o1,a01[j]); unpack2(o2,o3,a23[j]); unpack2(o4,o5,a45[j]);
        float vals[7] = {o0,o1,o2,o3,o4,o5,a6[j]};
        #pragma unroll
        for (int k=0;k<K_;k++)
            g_nb[((size_t)(k*B_+b)*N_ + n)*D_ + d] = vals[k];
    }
}

// ---------------- fold ----------------
__global__ void fold_kernel(const float* __restrict__ x, float* __restrict__ out)
{
    int idx = blockIdx.x*blockDim.x + threadIdx.x;
    const int total = B_*(K_+1)*CIN_*H_*W_;
    if (idx >= total) return;
    int w  = idx % W_;
    int r  = (idx / W_) % H_;
    int ch = (idx / (H_*W_)) % ((K_+1)*CIN_);
    int b  = idx / (H_*W_*(K_+1)*CIN_);

    if (ch < CIN_){
        out[idx] = x[((b*CIN_+ch)*H_+r)*W_+w];
        return;
    }
    int k = (ch - CIN_) / CIN_;
    int c = (ch - CIN_) % CIN_;

    int n1lo = (r >= P_-1) ? (r-(P_-1)+S_-1)/S_ : 0;
    int n1hi = min(N1_-1, r/S_);
    int n2lo = (w >= P_-1) ? (w-(P_-1)+S_-1)/S_ : 0;
    int n2hi = min(N1_-1, w/S_);

    float sum = 0.f; int cnt = 0;
    for (int n1=n1lo; n1<=n1hi; n1++){
        int p1 = r - n1*S_;
        for (int n2=n2lo; n2<=n2hi; n2++){
            int p2 = w - n2*S_;
            sum += g_nb[((size_t)(k*B_+b)*N_ + n1*N1_+n2)*D_ + c*100 + p1*10 + p2];
            cnt++;
        }
    }
    out[idx] = (cnt > 0) ? sum/(float)cnt : 0.f;
}

// ---------------- launch ----------------
extern "C" void kernel_launch(void* const* d_in, const int* in_sizes, int n_in,
                              void* d_out, int out_size)
{
    const float* x   = (const float*)d_in[0];
    const float* w1e = (const float*)d_in[1];
    const float* b1e = (const float*)d_in[2];
    const float* w2e = (const float*)d_in[3];
    const float* b2e = (const float*)d_in[4];
    const float* w3e = (const float*)d_in[5];
    const float* b3e = (const float*)d_in[6];
    const float* w1t = (const float*)d_in[7];
    const float* b1t = (const float*)d_in[8];
    const float* w2t = (const float*)d_in[9];
    const float* b2t = (const float*)d_in[10];
    const float* w3t = (const float*)d_in[11];
    const float* b3t = (const float*)d_in[12];

    float *t1e, *t1t, *t2e, *t2t, *xe, *ltmap;
    cudaGetSymbolAddress((void**)&t1e,   g_t1e);
    cudaGetSymbolAddress((void**)&t1t,   g_t1t);
    cudaGetSymbolAddress((void**)&t2e,   g_t2e);
    cudaGetSymbolAddress((void**)&t2t,   g_t2t);
    cudaGetSymbolAddress((void**)&xe,    g_xe);
    cudaGetSymbolAddress((void**)&ltmap, g_ltmap);

    static int attr_done = 0;
    if (!attr_done){
        cudaFuncSetAttribute(nnblock_kernel,
                             cudaFuncAttributeMaxDynamicSharedMemorySize, 56*1024);
        cudaFuncSetAttribute(conv2_mma,
                             cudaFuncAttributeMaxDynamicSharedMemorySize, CSM_TOT);
        attr_done = 1;
    }

    conv1_fused<<<dim3(49,8,B_), 256>>>(x, w1e, b1e, t1e, w1t, b1t, t1t);
    wprep_kernel<<<18, 256>>>(w2e, w2t);
    nhwc_convert<<<dim3(4,226,8), 256>>>(t1e, t1t);
    conv2_mma<<<dim3(392,2,2), 256, CSM_TOT>>>(b2e, b2t);
    conv3x3_dual<<<dim3(49,2,B_), 256>>>(t2e, w3e, b3e, xe,    E_,
                                         t2t, w3t, b3t, ltmap, 1, F_, 0, 1);

    patches_kernel<<<B_*N_, 128>>>();
    nnblock_kernel<<<B_*N_, 256, (12800+800)*sizeof(float)>>>(x);

    const int total = B_*(K_+1)*CIN_*H_*W_;
    fold_kernel<<<(total+255)/256, 256>>>(x, (float*)d_out);
}

// round 10
// speedup vs baseline: 1.6578x; 1.1176x over previous
#include <cuda_runtime.h>
#include <cuda_bf16.h>
#include <math.h>
#include <stdint.h>

#define B_ 2
#define CIN_ 8
#define H_ 224
#define W_ 224
#define F_ 64
#define E_ 8
#define P_ 10
#define S_ 5
#define K_ 7
#define N1_ 43
#define N_ 1849
#define M_ 49
#define D_ 800

typedef unsigned long long ull;
__device__ __forceinline__ void ffma2(ull &d, ull a, ull b){
    asm("fma.rn.f32x2 %0, %1, %2, %0;" : "+l"(d) : "l"(a), "l"(b));
}
__device__ __forceinline__ ull pack2s(float x){
    ull r; asm("mov.b64 %0, {%1, %1};" : "=l"(r) : "f"(x)); return r;
}
__device__ __forceinline__ void unpack2(float &x, float &y, ull v){
    asm("mov.b64 {%0, %1}, %2;" : "=f"(x), "=f"(y) : "l"(v));
}

__device__ float g_t1e[B_*F_*H_*W_];
__device__ float g_t1t[B_*F_*H_*W_];
__device__ float g_t2e[B_*F_*H_*W_];
__device__ float g_t2t[B_*F_*H_*W_];
__device__ float g_xe[B_*E_*H_*W_];
__device__ float g_ltmap[B_*H_*W_];
__device__ float g_pe[B_*N_*D_];
__device__ float g_sq[B_*N_];
__device__ float g_ltm[B_*N_];
__device__ float g_nb[K_*B_*N_*D_];
__device__ __nv_bfloat16 g_nhwc_hi[4*226*226*64];
__device__ __nv_bfloat16 g_nhwc_lo[4*226*226*64];
__device__ __nv_bfloat16 g_bt_hi[2*9*64*64];
__device__ __nv_bfloat16 g_bt_lo[2*9*64*64];

__device__ __forceinline__ uint32_t smem_u32(const void* p){
    uint32_t a;
    asm("{ .reg .u64 t; cvta.to.shared.u64 t, %1; cvt.u32.u64 %0, t; }" : "=r"(a) : "l"(p));
    return a;
}
__device__ __forceinline__ void sts32(uint32_t addr, uint32_t v){
    asm volatile("st.shared.b32 [%0], %1;" :: "r"(addr), "r"(v) : "memory");
}
__device__ __forceinline__ void mma_bf16(float* d, const uint32_t* a, uint32_t b0, uint32_t b1){
    asm volatile("mma.sync.aligned.m16n8k16.row.col.f32.bf16.bf16.f32 "
        "{%0,%1,%2,%3}, {%4,%5,%6,%7}, {%8,%9}, {%0,%1,%2,%3};"
        : "+f"(d[0]),"+f"(d[1]),"+f"(d[2]),"+f"(d[3])
        : "r"(a[0]),"r"(a[1]),"r"(a[2]),"r"(a[3]), "r"(b0),"r"(b1));
}
#define LDSM4(r, addr) \
    asm volatile("ldmatrix.sync.aligned.m8n8.x4.shared.b16 {%0,%1,%2,%3}, [%4];" \
        : "=r"((r)[0]),"=r"((r)[1]),"=r"((r)[2]),"=r"((r)[3]) : "r"(addr))

// smem layout: halo hi [0,25920), halo lo [25920,51840), weight buf (3 shifts x hi/lo x 64 oc rows)
#define HALO_LO_OFF 25920            // 180*144
#define CW_OFF      51840
#define CSM_TOT     107136           // 51840 + 384*144

// ---------- weight hi/lo table prep ----------
__global__ void wprep_kernel(const float* __restrict__ w2e, const float* __restrict__ w2t)
{
    int ns = blockIdx.x;
    int net = ns / 9, s = ns % 9;
    int dr = s / 3, dc = s % 3;
    const float* w = net ? w2t : w2e;
    int tid = threadIdx.x;
    for (int j = 0; j < 16; j++){
        int idx = tid + j*256;
        int oc = idx >> 6, ic = idx & 63;
        float v = w[((oc*64 + ic)*3 + dr)*3 + dc];
        __nv_bfloat16 hi = __float2bfloat16_rn(v);
        g_bt_hi[ns*4096 + idx] = hi;
        g_bt_lo[ns*4096 + idx] = __float2bfloat16_rn(v - __bfloat162float(hi));
    }
}

// ---------- t1 planar fp32 -> padded NHWC bf16 hi/lo ----------
__global__ void nhwc_convert(const float* __restrict__ t1e, const float* __restrict__ t1t)
{
    __shared__ float s[64][33];
    int bn = blockIdx.x;
    int b = bn >> 1, net = bn & 1;
    int rp = blockIdx.y;
    int cp0 = blockIdx.z * 32;
    int tid = threadIdx.x, lane = tid & 31, wid = tid >> 5;
    int r = rp - 1;
    const float* src = (net ? t1t : t1e) + (size_t)b*F_*H_*W_;

    for (int ic = wid; ic < 64; ic += 8){
        int c = cp0 + lane - 1;
        float v = 0.f;
        if (r >= 0 && r < H_ && c >= 0 && c < W_)
            v = src[(size_t)ic*H_*W_ + r*W_ + c];
        s[ic][lane] = v;
    }
    __syncthreads();

    uint32_t* hi_w = (uint32_t*)g_nhwc_hi;
    uint32_t* lo_w = (uint32_t*)g_nhwc_lo;
    for (int j = 0; j < 4; j++){
        int w = tid + j*256;
        int p = w >> 5, wl = w & 31;
        int cp = cp0 + p;
        if (cp >= 226) continue;
        float v0 = s[2*wl][p], v1 = s[2*wl+1][p];
        __nv_bfloat16 h0 = __float2bfloat16_rn(v0), h1 = __float2bfloat16_rn(v1);
        __nv_bfloat16 l0 = __float2bfloat16_rn(v0 - __bfloat162float(h0));
        __nv_bfloat16 l1 = __float2bfloat16_rn(v1 - __bfloat162float(h1));
        uint32_t hp = (uint32_t)__bfloat16_as_ushort(h0) | ((uint32_t)__bfloat16_as_ushort(h1) << 16);
        uint32_t lp = (uint32_t)__bfloat16_as_ushort(l0) | ((uint32_t)__bfloat16_as_ushort(l1) << 16);
        size_t wi = ((size_t)(bn*226 + rp)*226 + cp)*32 + wl;
        hi_w[wi] = hp;
        lo_w[wi] = lp;
    }
}

// ---------- conv2: mma.sync + ldmatrix, 2 CTAs/SM, per-dr weight staging ----------
__global__ void __launch_bounds__(256, 2)
conv2_mma(const float* __restrict__ b2e, const float* __restrict__ b2t)
{
    extern __shared__ char smem[];
    int bx = blockIdx.x;
    int net = blockIdx.y, b = blockIdx.z;
    int bn = b*2 + net;
    int ty = bx / 14, tx = bx % 14;
    int r0 = ty*8, c0 = tx*16;
    int tid = threadIdx.x, lane = tid & 31, w = tid >> 5;
    uint32_t smb = smem_u32(smem);

    // stage halo: 10 rows x 18 cols, hi + lo (64 ic = 32 words per slot, stride 144B)
    const uint32_t* nh = (const uint32_t*)g_nhwc_hi;
    const uint32_t* nl = (const uint32_t*)g_nhwc_lo;
    for (int t = w; t < 360; t += 8){
        int arr = (t >= 180);
        int slot = arr ? t - 180 : t;
        int hr = slot / 18, hc = slot % 18;
        const uint32_t* src = (arr ? nl : nh) + ((size_t)(bn*226 + r0+hr)*226 + (c0+hc))*32;
        sts32(smb + (arr ? HALO_LO_OFF : 0) + slot*144 + lane*4, src[lane]);
    }

    float acc[8][4];
    #pragma unroll
    for (int nt=0;nt<8;nt++)
        #pragma unroll
        for (int i=0;i<4;i++) acc[nt][i]=0.f;

    // ldmatrix per-thread row addresses
    int m15 = lane & 15;
    uint32_t a_base = smb + (uint32_t)(w*18 + m15)*144 + ((lane & 16) ? 16u : 0u);
    int ocb = (lane & 7) + ((lane & 16) ? 8 : 0);
    uint32_t b_base = smb + CW_OFF + (uint32_t)ocb*144 + ((lane & 8) ? 16u : 0u);

    const uint32_t* bth = (const uint32_t*)g_bt_hi + (size_t)net*9*64*32;
    const uint32_t* btl = (const uint32_t*)g_bt_lo + (size_t)net*9*64*32;

    for (int dr = 0; dr < 3; dr++){
        __syncthreads();   // all warps done with previous weight group (and halo stores before dr=0 compute)
        // stage weights for shifts dr*3 .. dr*3+2: row = sg*128 + hl*64 + oc
        for (int rr = w; rr < 384; rr += 8){
            int sg = rr >> 7, hl = (rr >> 6) & 1, oc = rr & 63;
            const uint32_t* src = (hl ? btl : bth) + ((size_t)(dr*3 + sg)*2048 + oc*32 + lane);
            sts32(smb + CW_OFF + rr*144 + lane*4, *src);
        }
        __syncthreads();

        for (int dc = 0; dc < 3; dc++){
            uint32_t a_off = a_base + (uint32_t)(dr*18 + dc)*144;
            uint32_t b_off = b_base + (uint32_t)(dc*128)*144;
            #pragma unroll
            for (int ks = 0; ks < 4; ks++){
                uint32_t ah[4], al[4];
                LDSM4(ah, a_off + ks*32);
                LDSM4(al, a_off + HALO_LO_OFF + ks*32);
                #pragma unroll
                for (int p = 0; p < 4; p++){
                    uint32_t wh[4], wl[4];
                    LDSM4(wh, b_off + (uint32_t)(p*16)*144 + ks*32);
                    LDSM4(wl, b_off + (uint32_t)(64 + p*16)*144 + ks*32);
                    mma_bf16(acc[2*p],   ah, wh[0], wh[1]);   // hi*hi
                    mma_bf16(acc[2*p],   ah, wl[0], wl[1]);   // hi*lo
                    mma_bf16(acc[2*p],   al, wh[0], wh[1]);   // lo*hi
                    mma_bf16(acc[2*p+1], ah, wh[2], wh[3]);
                    mma_bf16(acc[2*p+1], ah, wl[2], wl[3]);
                    mma_bf16(acc[2*p+1], al, wh[2], wh[3]);
                }
            }
        }
    }

    // epilogue: D rows = pixels, cols = oc
    const float* bias = net ? b2t : b2e;
    float* outp = (net ? g_t2t : g_t2e) + (size_t)b*F_*H_*W_;
    int orow = r0 + w;
    int pc = lane >> 2;
    int oc_b = (lane & 3) * 2;
    #pragma unroll
    for (int nt = 0; nt < 8; nt++){
        int oc = nt*8 + oc_b;
        float bv0 = bias[oc], bv1 = bias[oc+1];
        size_t base0 = (size_t)oc*(H_*W_) + (size_t)orow*W_ + c0;
        outp[base0 + pc]               = fmaxf(acc[nt][0] + bv0, 0.f);
        outp[base0 + H_*W_ + pc]       = fmaxf(acc[nt][1] + bv1, 0.f);
        outp[base0 + pc + 8]           = fmaxf(acc[nt][2] + bv0, 0.f);
        outp[base0 + H_*W_ + pc + 8]   = fmaxf(acc[nt][3] + bv1, 0.f);
    }
}

// ============ conv1 fused (FFMA2) ============
__global__ void __launch_bounds__(256, 2) conv1_fused(
    const float* __restrict__ x,
    const float* __restrict__ wA, const float* __restrict__ bA, float* __restrict__ outA,
    const float* __restrict__ wB, const float* __restrict__ bB, float* __restrict__ outB)
{
    __shared__ float s_in[2][34*34];
    __shared__ __align__(8) float s_w[2][9*16];
    int b = blockIdx.z, oc0 = blockIdx.y * 8;
    int tile = blockIdx.x, tx = tile % 7, ty = tile / 7;
    int x0 = tx*32, y0 = ty*32;
    int tid = threadIdx.x, lx = tid & 31, ly = tid >> 5;

    int goff[5];
    #pragma unroll
    for (int j=0;j<5;j++){
        int i = tid + j*256; goff[j] = -1;
        if (i < 34*34){
            int r = i/34, c = i%34, gr = y0-1+r, gc = x0-1+c;
            goff[j] = (gr>=0 && gr<H_ && gc>=0 && gc<W_) ? gr*W_+gc : -1;
        }
    }
    const float* inbase = x + (size_t)b*CIN_*H_*W_;
    const float* wp = wA; int wslot = 0;
    if (tid < 144){
        int o = tid/9, kk = tid%9;
        wslot = kk*16 + o;
        wp = (o < 8) ? (wA + ((oc0+o)*CIN_)*9 + kk)
                     : (wB + ((oc0+o-8)*CIN_)*9 + kk);
    }
    {
        #pragma unroll
        for (int j=0;j<5;j++){
            int i = tid + j*256;
            if (i < 34*34) s_in[0][i] = (goff[j] >= 0) ? inbase[goff[j]] : 0.f;
        }
        if (tid < 144) s_w[0][wslot] = wp[0];
    }
    __syncthreads();

    ull acc[4][8];
    #pragma unroll
    for (int p=0;p<4;p++)
        #pragma unroll
        for (int o=0;o<8;o++) acc[p][o]=0ull;

    for (int ic=0; ic<CIN_; ic++){
        int buf = ic & 1;
        if (ic+1 < CIN_){
            const float* inp = inbase + (size_t)(ic+1)*H_*W_;
            int nb = buf^1;
            #pragma unroll
            for (int j=0;j<5;j++){
                int i = tid + j*256;
                if (i < 34*34) s_in[nb][i] = (goff[j] >= 0) ? inp[goff[j]] : 0.f;
            }
            if (tid < 144) s_w[nb][wslot] = wp[(ic+1)*9];
        }
        const float* si = s_in[buf];
        #pragma unroll
        for (int dr=0;dr<3;dr++){
            #pragma unroll
            for (int dc=0;dc<3;dc++){
                int kk = dr*3+dc;
                ull v0 = pack2s(si[(ly   +dr)*34 + lx+dc]);
                ull v1 = pack2s(si[(ly+ 8+dr)*34 + lx+dc]);
                ull v2 = pack2s(si[(ly+16+dr)*34 + lx+dc]);
                ull v3 = pack2s(si[(ly+24+dr)*34 + lx+dc]);
                const ull* wrow = (const ull*)&s_w[buf][kk*16];
                #pragma unroll
                for (int op=0;op<8;op++){
                    ull w2 = wrow[op];
                    ffma2(acc[0][op], v0, w2);
                    ffma2(acc[1][op], v1, w2);
                    ffma2(acc[2][op], v2, w2);
                    ffma2(acc[3][op], v3, w2);
                }
            }
        }
        __syncthreads();
    }

    #pragma unroll
    for (int op=0;op<8;op++){
        #pragma unroll
        for (int h=0;h<2;h++){
            int o = op*2+h;
            int oc = oc0 + ((o<8) ? o : o-8);
            float bv = (o<8) ? bA[oc] : bB[oc];
            float* opt = (o<8) ? outA : outB;
            #pragma unroll
            for (int p=0;p<4;p++){
                float a0,a1; unpack2(a0,a1,acc[p][op]);
                float r = fmaxf((h ? a1 : a0) + bv, 0.f);
                opt[((size_t)(b*F_+oc)*H_ + (y0+ly+p*8))*W_ + x0+lx] = r;
            }
        }
    }
}

// ---------------- dual 3x3 conv (layer 3), FFMA2 ----------------
__global__ void __launch_bounds__(256, 4) conv3x3_dual(
    const float* __restrict__ inA, const float* __restrict__ wA,
    const float* __restrict__ bA, float* __restrict__ outA, int CoutA,
    const float* __restrict__ inB, const float* __restrict__ wB,
    const float* __restrict__ bB, float* __restrict__ outB, int CoutB,
    int Cin, int relu, int gA)
{
    __shared__ float s_in[34*34];
    __shared__ __align__(8) float s_w[9*8];
    int b = blockIdx.z, ocg = blockIdx.y;
    const float* in; const float* wgt; const float* bias; float* out; int Cout;
    if (ocg < gA){ in=inA; wgt=wA; bias=bA; out=outA; Cout=CoutA; }
    else { ocg -= gA; in=inB; wgt=wB; bias=bB; out=outB; Cout=CoutB; }

    int tile = blockIdx.x, tx = tile % 7, ty = tile / 7;
    int x0 = tx*32, y0 = ty*32;
    int tid = threadIdx.x, lx = tid & 31, ly = tid >> 5;

    ull acc[4][4];
    #pragma unroll
    for (int p=0;p<4;p++)
        #pragma unroll
        for (int o=0;o<4;o++) acc[p][o]=0ull;

    for (int ic=0; ic<Cin; ic++){
        const float* inp = in + ((size_t)(b*Cin + ic))*H_*W_;
        for (int i=tid; i<34*34; i+=256){
            int r = i/34, c = i%34, gr = y0-1+r, gc = x0-1+c;
            float v = 0.f;
            if (gr>=0 && gr<H_ && gc>=0 && gc<W_) v = inp[gr*W_+gc];
            s_in[i] = v;
        }
        if (tid < 72){
            int o = tid/9, kk = tid%9;
            int oc = ocg*8+o;
            s_w[kk*8+o] = (oc<Cout) ? wgt[(oc*Cin+ic)*9 + kk] : 0.f;
        }
        __syncthreads();
        #pragma unroll
        for (int dr=0;dr<3;dr++){
            #pragma unroll
            for (int dc=0;dc<3;dc++){
                int kk = dr*3+dc;
                ull v0 = pack2s(s_in[(ly   +dr)*34 + lx+dc]);
                ull v1 = pack2s(s_in[(ly+ 8+dr)*34 + lx+dc]);
                ull v2 = pack2s(s_in[(ly+16+dr)*34 + lx+dc]);
                ull v3 = pack2s(s_in[(ly+24+dr)*34 + lx+dc]);
                const ull* wrow = (const ull*)&s_w[kk*8];
                #pragma unroll
                for (int op=0;op<4;op++){
                    ull w2 = wrow[op];
                    ffma2(acc[0][op], v0, w2);
                    ffma2(acc[1][op], v1, w2);
                    ffma2(acc[2][op], v2, w2);
                    ffma2(acc[3][op], v3, w2);
                }
            }
        }
        __syncthreads();
    }

    #pragma unroll
    for (int op=0;op<4;op++){
        #pragma unroll
        for (int h=0;h<2;h++){
            int o = op*2+h;
            int oc = ocg*8+o;
            if (oc < Cout){
                float bv = bias[oc];
                #pragma unroll
                for (int p=0;p<4;p++){
                    float a0,a1; unpack2(a0,a1,acc[p][op]);
                    float r = (h ? a1 : a0) + bv;
                    if (relu) r = fmaxf(r, 0.f);
                    out[((size_t)(b*Cout+oc)*H_ + (y0+ly+p*8))*W_ + x0+lx] = r;
                }
            }
        }
    }
}

// ---------------- patches ----------------
__global__ void patches_kernel()
{
    int bn = blockIdx.x;
    int b = bn / N_, n = bn % N_;
    int n1 = n / N1_, n2 = n % N1_;
    int r0 = n1*S_, c0 = n2*S_;
    int tid = threadIdx.x;

    float loc = 0.f;
    for (int d=tid; d<D_; d+=128){
        int c = d/100, rem = d%100, p1 = rem/10, p2 = rem%10;
        float v = g_xe[((b*E_+c)*H_ + r0+p1)*W_ + c0+p2];
        g_pe[(size_t)bn*D_ + d] = v;
        loc += v*v;
    }
    float lv = 0.f;
    if (tid < 100){
        int p1 = tid/10, p2 = tid%10;
        lv = g_ltmap[(b*H_ + r0+p1)*W_ + c0+p2];
    }
    __shared__ float r1s[4], r2s[4];
    int lane = tid & 31, wid = tid >> 5;
    #pragma unroll
    for (int off=16; off; off>>=1){
        loc += __shfl_xor_sync(0xffffffffu, loc, off);
        lv  += __shfl_xor_sync(0xffffffffu, lv,  off);
    }
    if (lane==0){ r1s[wid]=loc; r2s[wid]=lv; }
    __syncthreads();
    if (tid==0){
        g_sq[bn]  = r1s[0]+r1s[1]+r1s[2]+r1s[3];
        g_ltm[bn] = (r2s[0]+r2s[1]+r2s[2]+r2s[3]) * (1.f/100.f);
    }
}

// ------- nnblock -------
__global__ void __launch_bounds__(256) nnblock_kernel(const float* __restrict__ x)
{
    extern __shared__ float sm[];
    float* s_xf = sm;
    float* s_q  = sm + 12800;
    __shared__ __align__(8) float s_wk[M_][8];
    __shared__ float s_logit[M_];
    __shared__ int   s_cand[M_];
    __shared__ int   s_off[M_];

    int bn = blockIdx.x;
    int b = bn / N_, n = bn % N_;
    int q1 = n / N1_, q2 = n % N1_;
    int tid = threadIdx.x, lane = tid & 31, wid = tid >> 5;

    int c1lo = max(q1-3,0), c1hi = min(q1+3, N1_-1);
    int c2lo = max(q2-3,0), c2hi = min(q2+3, N1_-1);
    int rows = (c1hi-c1lo)*S_ + P_;
    int cols = (c2hi-c2lo)*S_ + P_;
    int r0 = c1lo*S_, c0 = c2lo*S_;

    if (tid < M_){
        int i = tid/7, j = tid%7;
        int c1 = min(max(q1+i-3,0), N1_-1);
        int c2 = min(max(q2+j-3,0), N1_-1);
        s_cand[tid] = c1*N1_ + c2;
        s_off[tid]  = ((c1-c1lo)*S_)*40 + (c2-c2lo)*S_;
    }
    if (tid < 200)
        ((float4*)s_q)[tid] = ((const float4*)(g_pe + (size_t)bn*D_))[tid];

    #pragma unroll
    for (int c=0;c<CIN_;c++){
        const float* src = x + ((size_t)(b*CIN_+c)*H_ + r0)*W_ + c0;
        for (int r=wid; r<rows; r+=8)
            for (int cc=lane; cc<cols; cc+=32)
                s_xf[c*1600 + r*40 + cc] = src[r*W_ + cc];
    }
    __syncthreads();

    float sq_q  = g_sq[bn];
    float scale = expf(-g_ltm[bn]);

    const float4* sq4 = (const float4*)s_q;
    for (int m=wid; m<M_; m+=8){
        int cand = s_cand[m];
        const float4* pc = (const float4*)(g_pe + (size_t)(b*N_+cand)*D_);
        float s0=0.f, s1=0.f, s2=0.f, s3=0.f;
        #pragma unroll
        for (int j=0;j<6;j++){
            float4 a = pc[lane + j*32];
            float4 q = sq4[lane + j*32];
            s0 = fmaf(a.x,q.x,s0); s1 = fmaf(a.y,q.y,s1);
            s2 = fmaf(a.z,q.z,s2); s3 = fmaf(a.w,q.w,s3);
        }
        if (lane < 8){
            float4 a = pc[192+lane];
            float4 q = sq4[192+lane];
            s0 = fmaf(a.x,q.x,s0); s1 = fmaf(a.y,q.y,s1);
            s2 = fmaf(a.z,q.z,s2); s3 = fmaf(a.w,q.w,s3);
        }
        float s = (s0+s1)+(s2+s3);
        #pragma unroll
        for (int off=16; off; off>>=1) s += __shfl_xor_sync(0xffffffffu, s, off);
        if (lane==0){
            float Dv = -(sq_q + g_sq[b*N_+cand] - 2.f*s);
            s_logit[m] = (cand==n) ? -1e9f : Dv*scale;
        }
    }
    __syncthreads();

    if (tid < 32){
        float a = s_logit[tid];
        bool hasb = (tid+32) < M_;
        float bvl = hasb ? s_logit[tid+32] : -INFINITY;
        #pragma unroll
        for (int k=0;k<K_;k++){
            float mx = fmaxf(a, bvl);
            #pragma unroll
            for (int off=16; off; off>>=1) mx = fmaxf(mx, __shfl_xor_sync(0xffffffffu, mx, off));
            float ea = expf(a - mx);
            float eb = hasb ? expf(bvl - mx) : 0.f;
            float ssum = ea + eb;
            #pragma unroll
            for (int off=16; off; off>>=1) ssum += __shfl_xor_sync(0xffffffffu, ssum, off);
            float inv = 1.f/ssum;
            float wa = ea*inv, wb = eb*inv;
            s_wk[tid][k] = wa;
            if (hasb) s_wk[tid+32][k] = wb;
            a   += log1pf(-fminf(wa, 1.f-1e-6f));
            bvl += log1pf(-fminf(wb, 1.f-1e-6f));
        }
    }
    __syncthreads();

    int baseidx[4]; bool act[4];
    #pragma unroll
    for (int j=0;j<4;j++){
        int d = tid + 256*j;
        act[j] = (d < D_);
        int dd = act[j] ? d : 0;
        int c = dd/100, rem = dd%100, p1 = rem/10, p2 = rem%10;
        baseidx[j] = c*1600 + p1*40 + p2;
    }
    ull a01[4], a23[4], a45[4];
    float a6[4];
    #pragma unroll
    for (int j=0;j<4;j++){ a01[j]=0ull; a23[j]=0ull; a45[j]=0ull; a6[j]=0.f; }

    for (int m=0;m<M_;m++){
        int o = s_off[m];
        const ull* wr = (const ull*)&s_wk[m][0];
        ull w01 = wr[0], w23 = wr[1], w45 = wr[2];
        float w6 = s_wk[m][6];
        #pragma unroll
        for (int j=0;j<4;j++){
            float v = s_xf[baseidx[j]+o];
            ull vv = pack2s(v);
            ffma2(a01[j], vv, w01);
            ffma2(a23[j], vv, w23);
            ffma2(a45[j], vv, w45);
            a6[j] = fmaf(w6, v, a6[j]);
        }
    }
    #pragma unroll
    for (int j=0;j<4;j++){
        if (!act[j]) continue;
        int d = tid + 256*j;
        float o0,o1,o2,o3,o4,o5;
        unpack2(o0,o1,a01[j]); unpack2(o2,o3,a23[j]); unpack2(o4,o5,a45[j]);
        float vals[7] = {o0,o1,o2,o3,o4,o5,a6[j]};
        #pragma unroll
        for (int k=0;k<K_;k++)
            g_nb[((size_t)(k*B_+b)*N_ + n)*D_ + d] = vals[k];
    }
}

// ---------------- fold ----------------
__global__ void fold_kernel(const float* __restrict__ x, float* __restrict__ out)
{
    int idx = blockIdx.x*blockDim.x + threadIdx.x;
    const int total = B_*(K_+1)*CIN_*H_*W_;
    if (idx >= total) return;
    int w  = idx % W_;
    int r  = (idx / W_) % H_;
    int ch = (idx / (H_*W_)) % ((K_+1)*CIN_);
    int b  = idx / (H_*W_*(K_+1)*CIN_);

    if (ch < CIN_){
        out[idx] = x[((b*CIN_+ch)*H_+r)*W_+w];
        return;
    }
    int k = (ch - CIN_) / CIN_;
    int c = (ch - CIN_) % CIN_;

    int n1lo = (r >= P_-1) ? (r-(P_-1)+S_-1)/S_ : 0;
    int n1hi = min(N1_-1, r/S_);
    int n2lo = (w >= P_-1) ? (w-(P_-1)+S_-1)/S_ : 0;
    int n2hi = min(N1_-1, w/S_);

    float sum = 0.f; int cnt = 0;
    for (int n1=n1lo; n1<=n1hi; n1++){
        int p1 = r - n1*S_;
        for (int n2=n2lo; n2<=n2hi; n2++){
            int p2 = w - n2*S_;
            sum += g_nb[((size_t)(k*B_+b)*N_ + n1*N1_+n2)*D_ + c*100 + p1*10 + p2];
            cnt++;
        }
    }
    out[idx] = (cnt > 0) ? sum/(float)cnt : 0.f;
}

// ---------------- launch ----------------
extern "C" void kernel_launch(void* const* d_in, const int* in_sizes, int n_in,
                              void* d_out, int out_size)
{
    const float* x   = (const float*)d_in[0];
    const float* w1e = (const float*)d_in[1];
    const float* b1e = (const float*)d_in[2];
    const float* w2e = (const float*)d_in[3];
    const float* b2e = (const float*)d_in[4];
    const float* w3e = (const float*)d_in[5];
    const float* b3e = (const float*)d_in[6];
    const float* w1t = (const float*)d_in[7];
    const float* b1t = (const float*)d_in[8];
    const float* w2t = (const float*)d_in[9];
    const float* b2t = (const float*)d_in[10];
    const float* w3t = (const float*)d_in[11];
    const float* b3t = (const float*)d_in[12];

    float *t1e, *t1t, *t2e, *t2t, *xe, *ltmap;
    cudaGetSymbolAddress((void**)&t1e,   g_t1e);
    cudaGetSymbolAddress((void**)&t1t,   g_t1t);
    cudaGetSymbolAddress((void**)&t2e,   g_t2e);
    cudaGetSymbolAddress((void**)&t2t,   g_t2t);
    cudaGetSymbolAddress((void**)&xe,    g_xe);
    cudaGetSymbolAddress((void**)&ltmap, g_ltmap);

    static int attr_done = 0;
    if (!attr_done){
        cudaFuncSetAttribute(nnblock_kernel,
                             cudaFuncAttributeMaxDynamicSharedMemorySize, 56*1024);
        cudaFuncSetAttribute(conv2_mma,
                             cudaFuncAttributeMaxDynamicSharedMemorySize, CSM_TOT);
        attr_done = 1;
    }

    conv1_fused<<<dim3(49,8,B_), 256>>>(x, w1e, b1e, t1e, w1t, b1t, t1t);
    wprep_kernel<<<18, 256>>>(w2e, w2t);
    nhwc_convert<<<dim3(4,226,8), 256>>>(t1e, t1t);
    conv2_mma<<<dim3(392,2,2), 256, CSM_TOT>>>(b2e, b2t);
    conv3x3_dual<<<dim3(49,2,B_), 256>>>(t2e, w3e, b3e, xe,    E_,
                                         t2t, w3t, b3t, ltmap, 1, F_, 0, 1);

    patches_kernel<<<B_*N_, 128>>>();
    nnblock_kernel<<<B_*N_, 256, (12800+800)*sizeof(float)>>>(x);

    const int total = B_*(K_+1)*CIN_*H_*W_;
    fold_kernel<<<(total+255)/256, 256>>>(x, (float*)d_out);
}

// round 11
// speedup vs baseline: 1.7602x; 1.0618x over previous
#include <cuda_runtime.h>
#include <cuda_bf16.h>
#include <math.h>
#include <stdint.h>

#define B_ 2
#define CIN_ 8
#define H_ 224
#define W_ 224
#define F_ 64
#define E_ 8
#define P_ 10
#define S_ 5
#define K_ 7
#define N1_ 43
#define N_ 1849
#define M_ 49
#define D_ 800

typedef unsigned long long ull;
__device__ __forceinline__ void ffma2(ull &d, ull a, ull b){
    asm("fma.rn.f32x2 %0, %1, %2, %0;" : "+l"(d) : "l"(a), "l"(b));
}
__device__ __forceinline__ ull pack2s(float x){
    ull r; asm("mov.b64 %0, {%1, %1};" : "=l"(r) : "f"(x)); return r;
}
__device__ __forceinline__ void unpack2(float &x, float &y, ull v){
    asm("mov.b64 {%0, %1}, %2;" : "=f"(x), "=f"(y) : "l"(v));
}

__device__ float g_t1e[B_*F_*H_*W_];
__device__ float g_t1t[B_*F_*H_*W_];
__device__ float g_t2e[B_*F_*H_*W_];
__device__ float g_t2t[B_*F_*H_*W_];
__device__ float g_xe[B_*E_*H_*W_];
__device__ float g_ltmap[B_*H_*W_];
__device__ float g_pe[B_*N_*D_];
__device__ float g_sq[B_*N_];
__device__ float g_ltm[B_*N_];
__device__ float g_nb[K_*B_*N_*D_];
__device__ __nv_bfloat16 g_nhwc_hi[4*226*226*64];
__device__ __nv_bfloat16 g_nhwc_lo[4*226*226*64];
__device__ __nv_bfloat16 g_bt_hi[2*9*64*64];
__device__ __nv_bfloat16 g_bt_lo[2*9*64*64];

__device__ __forceinline__ uint32_t smem_u32(const void* p){
    uint32_t a;
    asm("{ .reg .u64 t; cvta.to.shared.u64 t, %1; cvt.u32.u64 %0, t; }" : "=r"(a) : "l"(p));
    return a;
}
__device__ __forceinline__ void sts32(uint32_t addr, uint32_t v){
    asm volatile("st.shared.b32 [%0], %1;" :: "r"(addr), "r"(v) : "memory");
}
__device__ __forceinline__ void mma_bf16(float* d, const uint32_t* a, uint32_t b0, uint32_t b1){
    asm volatile("mma.sync.aligned.m16n8k16.row.col.f32.bf16.bf16.f32 "
        "{%0,%1,%2,%3}, {%4,%5,%6,%7}, {%8,%9}, {%0,%1,%2,%3};"
        : "+f"(d[0]),"+f"(d[1]),"+f"(d[2]),"+f"(d[3])
        : "r"(a[0]),"r"(a[1]),"r"(a[2]),"r"(a[3]), "r"(b0),"r"(b1));
}
#define LDSM4(r, addr) \
    asm volatile("ldmatrix.sync.aligned.m8n8.x4.shared.b16 {%0,%1,%2,%3}, [%4];" \
        : "=r"((r)[0]),"=r"((r)[1]),"=r"((r)[2]),"=r"((r)[3]) : "r"(addr))

// conv2 smem: halo hi [0,46656), halo lo [46656,93312), weights (1 shift, hi 64 rows + lo 64 rows)
#define HALO_LO2 46656               // 324*144
#define CW2_OFF  93312
#define CSM2_TOT 111744              // 93312 + 128*144

// ---------- weight hi/lo table prep ----------
__global__ void wprep_kernel(const float* __restrict__ w2e, const float* __restrict__ w2t)
{
    int ns = blockIdx.x;
    int net = ns / 9, s = ns % 9;
    int dr = s / 3, dc = s % 3;
    const float* w = net ? w2t : w2e;
    int tid = threadIdx.x;
    for (int j = 0; j < 16; j++){
        int idx = tid + j*256;
        int oc = idx >> 6, ic = idx & 63;
        float v = w[((oc*64 + ic)*3 + dr)*3 + dc];
        __nv_bfloat16 hi = __float2bfloat16_rn(v);
        g_bt_hi[ns*4096 + idx] = hi;
        g_bt_lo[ns*4096 + idx] = __float2bfloat16_rn(v - __bfloat162float(hi));
    }
}

// ---------- t1 planar fp32 -> padded NHWC bf16 hi/lo ----------
__global__ void nhwc_convert(const float* __restrict__ t1e, const float* __restrict__ t1t)
{
    __shared__ float s[64][33];
    int bn = blockIdx.x;
    int b = bn >> 1, net = bn & 1;
    int rp = blockIdx.y;
    int cp0 = blockIdx.z * 32;
    int tid = threadIdx.x, lane = tid & 31, wid = tid >> 5;
    int r = rp - 1;
    const float* src = (net ? t1t : t1e) + (size_t)b*F_*H_*W_;

    for (int ic = wid; ic < 64; ic += 8){
        int c = cp0 + lane - 1;
        float v = 0.f;
        if (r >= 0 && r < H_ && c >= 0 && c < W_)
            v = src[(size_t)ic*H_*W_ + r*W_ + c];
        s[ic][lane] = v;
    }
    __syncthreads();

    uint32_t* hi_w = (uint32_t*)g_nhwc_hi;
    uint32_t* lo_w = (uint32_t*)g_nhwc_lo;
    for (int j = 0; j < 4; j++){
        int w = tid + j*256;
        int p = w >> 5, wl = w & 31;
        int cp = cp0 + p;
        if (cp >= 226) continue;
        float v0 = s[2*wl][p], v1 = s[2*wl+1][p];
        __nv_bfloat16 h0 = __float2bfloat16_rn(v0), h1 = __float2bfloat16_rn(v1);
        __nv_bfloat16 l0 = __float2bfloat16_rn(v0 - __bfloat162float(h0));
        __nv_bfloat16 l1 = __float2bfloat16_rn(v1 - __bfloat162float(h1));
        uint32_t hp = (uint32_t)__bfloat16_as_ushort(h0) | ((uint32_t)__bfloat16_as_ushort(h1) << 16);
        uint32_t lp = (uint32_t)__bfloat16_as_ushort(l0) | ((uint32_t)__bfloat16_as_ushort(l1) << 16);
        size_t wi = ((size_t)(bn*226 + rp)*226 + cp)*32 + wl;
        hi_w[wi] = hp;
        lo_w[wi] = lp;
    }
}

// ---------- conv2: mma.sync + ldmatrix, 16x16 tile, 2 rows/warp, per-shift weights ----------
__global__ void __launch_bounds__(256, 2)
conv2_mma(const float* __restrict__ b2e, const float* __restrict__ b2t)
{
    extern __shared__ char smem[];
    int bx = blockIdx.x;
    int net = blockIdx.y, b = blockIdx.z;
    int bn = b*2 + net;
    int ty = bx / 14, tx = bx % 14;
    int r0 = ty*16, c0 = tx*16;
    int tid = threadIdx.x, lane = tid & 31, w = tid >> 5;
    uint32_t smb = smem_u32(smem);

    // stage halo: 18 rows x 18 cols, hi + lo (64 ic = 32 words per slot, stride 144B)
    const uint32_t* nh = (const uint32_t*)g_nhwc_hi;
    const uint32_t* nl = (const uint32_t*)g_nhwc_lo;
    for (int t = w; t < 648; t += 8){
        int arr = (t >= 324);
        int slot = arr ? t - 324 : t;
        int hr = slot / 18, hc = slot % 18;
        const uint32_t* src = (arr ? nl : nh) + ((size_t)(bn*226 + r0+hr)*226 + (c0+hc))*32;
        sts32(smb + (arr ? HALO_LO2 : 0) + slot*144 + lane*4, src[lane]);
    }

    float acc[2][8][4];
    #pragma unroll
    for (int rr=0;rr<2;rr++)
        #pragma unroll
        for (int nt=0;nt<8;nt++)
            #pragma unroll
            for (int i=0;i<4;i++) acc[rr][nt][i]=0.f;

    // ldmatrix per-thread components
    int m15 = lane & 15;
    uint32_t a_t = smb + (uint32_t)m15*144 + ((lane & 16) ? 16u : 0u);
    int ocb = (lane & 7) + ((lane & 16) ? 8 : 0);
    uint32_t b_base = smb + CW2_OFF + (uint32_t)ocb*144 + ((lane & 8) ? 16u : 0u);

    const uint32_t* bth = (const uint32_t*)g_bt_hi + (size_t)net*9*64*32;
    const uint32_t* btl = (const uint32_t*)g_bt_lo + (size_t)net*9*64*32;

    for (int s = 0; s < 9; s++){
        int dr = s / 3, dc = s % 3;
        __syncthreads();   // previous weight buffer fully consumed (and halo ready before s=0)
        for (int rr = w; rr < 128; rr += 8){
            int hl = rr >> 6, oc = rr & 63;
            const uint32_t* src = (hl ? btl : bth) + ((size_t)s*2048 + oc*32 + lane);
            sts32(smb + CW2_OFF + rr*144 + lane*4, *src);
        }
        __syncthreads();

        // A row slots for this shift: (2w + rr + dr, m15 + dc)
        uint32_t a0 = a_t + (uint32_t)((2*w     + dr)*18 + dc)*144;
        uint32_t a1 = a_t + (uint32_t)((2*w + 1 + dr)*18 + dc)*144;
        #pragma unroll
        for (int ks = 0; ks < 4; ks++){
            uint32_t ah0[4], al0[4], ah1[4], al1[4];
            LDSM4(ah0, a0 + ks*32);
            LDSM4(al0, a0 + HALO_LO2 + ks*32);
            LDSM4(ah1, a1 + ks*32);
            LDSM4(al1, a1 + HALO_LO2 + ks*32);
            #pragma unroll
            for (int p = 0; p < 4; p++){
                uint32_t wh[4], wl[4];
                LDSM4(wh, b_base + (uint32_t)(p*16)*144 + ks*32);
                LDSM4(wl, b_base + (uint32_t)(64 + p*16)*144 + ks*32);
                mma_bf16(acc[0][2*p],   ah0, wh[0], wh[1]);
                mma_bf16(acc[0][2*p],   ah0, wl[0], wl[1]);
                mma_bf16(acc[0][2*p],   al0, wh[0], wh[1]);
                mma_bf16(acc[0][2*p+1], ah0, wh[2], wh[3]);
                mma_bf16(acc[0][2*p+1], ah0, wl[2], wl[3]);
                mma_bf16(acc[0][2*p+1], al0, wh[2], wh[3]);
                mma_bf16(acc[1][2*p],   ah1, wh[0], wh[1]);
                mma_bf16(acc[1][2*p],   ah1, wl[0], wl[1]);
                mma_bf16(acc[1][2*p],   al1, wh[0], wh[1]);
                mma_bf16(acc[1][2*p+1], ah1, wh[2], wh[3]);
                mma_bf16(acc[1][2*p+1], ah1, wl[2], wl[3]);
                mma_bf16(acc[1][2*p+1], al1, wh[2], wh[3]);
            }
        }
    }

    // epilogue: rows r0+2w+rr, cols c0..c0+15, oc per fragment mapping
    const float* bias = net ? b2t : b2e;
    float* outp = (net ? g_t2t : g_t2e) + (size_t)b*F_*H_*W_;
    int pc = lane >> 2;
    int oc_b = (lane & 3) * 2;
    #pragma unroll
    for (int rr = 0; rr < 2; rr++){
        int orow = r0 + 2*w + rr;
        #pragma unroll
        for (int nt = 0; nt < 8; nt++){
            int oc = nt*8 + oc_b;
            float bv0 = bias[oc], bv1 = bias[oc+1];
            size_t base0 = (size_t)oc*(H_*W_) + (size_t)orow*W_ + c0;
            outp[base0 + pc]               = fmaxf(acc[rr][nt][0] + bv0, 0.f);
            outp[base0 + H_*W_ + pc]       = fmaxf(acc[rr][nt][1] + bv1, 0.f);
            outp[base0 + pc + 8]           = fmaxf(acc[rr][nt][2] + bv0, 0.f);
            outp[base0 + H_*W_ + pc + 8]   = fmaxf(acc[rr][nt][3] + bv1, 0.f);
        }
    }
}

// ============ conv1 fused (FFMA2) ============
__global__ void __launch_bounds__(256, 2) conv1_fused(
    const float* __restrict__ x,
    const float* __restrict__ wA, const float* __restrict__ bA, float* __restrict__ outA,
    const float* __restrict__ wB, const float* __restrict__ bB, float* __restrict__ outB)
{
    __shared__ float s_in[2][34*34];
    __shared__ __align__(8) float s_w[2][9*16];
    int b = blockIdx.z, oc0 = blockIdx.y * 8;
    int tile = blockIdx.x, tx = tile % 7, ty = tile / 7;
    int x0 = tx*32, y0 = ty*32;
    int tid = threadIdx.x, lx = tid & 31, ly = tid >> 5;

    int goff[5];
    #pragma unroll
    for (int j=0;j<5;j++){
        int i = tid + j*256; goff[j] = -1;
        if (i < 34*34){
            int r = i/34, c = i%34, gr = y0-1+r, gc = x0-1+c;
            goff[j] = (gr>=0 && gr<H_ && gc>=0 && gc<W_) ? gr*W_+gc : -1;
        }
    }
    const float* inbase = x + (size_t)b*CIN_*H_*W_;
    const float* wp = wA; int wslot = 0;
    if (tid < 144){
        int o = tid/9, kk = tid%9;
        wslot = kk*16 + o;
        wp = (o < 8) ? (wA + ((oc0+o)*CIN_)*9 + kk)
                     : (wB + ((oc0+o-8)*CIN_)*9 + kk);
    }
    {
        #pragma unroll
        for (int j=0;j<5;j++){
            int i = tid + j*256;
            if (i < 34*34) s_in[0][i] = (goff[j] >= 0) ? inbase[goff[j]] : 0.f;
        }
        if (tid < 144) s_w[0][wslot] = wp[0];
    }
    __syncthreads();

    ull acc[4][8];
    #pragma unroll
    for (int p=0;p<4;p++)
        #pragma unroll
        for (int o=0;o<8;o++) acc[p][o]=0ull;

    for (int ic=0; ic<CIN_; ic++){
        int buf = ic & 1;
        if (ic+1 < CIN_){
            const float* inp = inbase + (size_t)(ic+1)*H_*W_;
            int nb = buf^1;
            #pragma unroll
            for (int j=0;j<5;j++){
                int i = tid + j*256;
                if (i < 34*34) s_in[nb][i] = (goff[j] >= 0) ? inp[goff[j]] : 0.f;
            }
            if (tid < 144) s_w[nb][wslot] = wp[(ic+1)*9];
        }
        const float* si = s_in[buf];
        #pragma unroll
        for (int dr=0;dr<3;dr++){
            #pragma unroll
            for (int dc=0;dc<3;dc++){
                int kk = dr*3+dc;
                ull v0 = pack2s(si[(ly   +dr)*34 + lx+dc]);
                ull v1 = pack2s(si[(ly+ 8+dr)*34 + lx+dc]);
                ull v2 = pack2s(si[(ly+16+dr)*34 + lx+dc]);
                ull v3 = pack2s(si[(ly+24+dr)*34 + lx+dc]);
                const ull* wrow = (const ull*)&s_w[buf][kk*16];
                #pragma unroll
                for (int op=0;op<8;op++){
                    ull w2 = wrow[op];
                    ffma2(acc[0][op], v0, w2);
                    ffma2(acc[1][op], v1, w2);
                    ffma2(acc[2][op], v2, w2);
                    ffma2(acc[3][op], v3, w2);
                }
            }
        }
        __syncthreads();
    }

    #pragma unroll
    for (int op=0;op<8;op++){
        #pragma unroll
        for (int h=0;h<2;h++){
            int o = op*2+h;
            int oc = oc0 + ((o<8) ? o : o-8);
            float bv = (o<8) ? bA[oc] : bB[oc];
            float* opt = (o<8) ? outA : outB;
            #pragma unroll
            for (int p=0;p<4;p++){
                float a0,a1; unpack2(a0,a1,acc[p][op]);
                float r = fmaxf((h ? a1 : a0) + bv, 0.f);
                opt[((size_t)(b*F_+oc)*H_ + (y0+ly+p*8))*W_ + x0+lx] = r;
            }
        }
    }
}

// ---------------- dual 3x3 conv (layer 3), FFMA2 ----------------
__global__ void __launch_bounds__(256, 4) conv3x3_dual(
    const float* __restrict__ inA, const float* __restrict__ wA,
    const float* __restrict__ bA, float* __restrict__ outA, int CoutA,
    const float* __restrict__ inB, const float* __restrict__ wB,
    const float* __restrict__ bB, float* __restrict__ outB, int CoutB,
    int Cin, int relu, int gA)
{
    __shared__ float s_in[34*34];
    __shared__ __align__(8) float s_w[9*8];
    int b = blockIdx.z, ocg = blockIdx.y;
    const float* in; const float* wgt; const float* bias; float* out; int Cout;
    if (ocg < gA){ in=inA; wgt=wA; bias=bA; out=outA; Cout=CoutA; }
    else { ocg -= gA; in=inB; wgt=wB; bias=bB; out=outB; Cout=CoutB; }

    int tile = blockIdx.x, tx = tile % 7, ty = tile / 7;
    int x0 = tx*32, y0 = ty*32;
    int tid = threadIdx.x, lx = tid & 31, ly = tid >> 5;

    ull acc[4][4];
    #pragma unroll
    for (int p=0;p<4;p++)
        #pragma unroll
        for (int o=0;o<4;o++) acc[p][o]=0ull;

    for (int ic=0; ic<Cin; ic++){
        const float* inp = in + ((size_t)(b*Cin + ic))*H_*W_;
        for (int i=tid; i<34*34; i+=256){
            int r = i/34, c = i%34, gr = y0-1+r, gc = x0-1+c;
            float v = 0.f;
            if (gr>=0 && gr<H_ && gc>=0 && gc<W_) v = inp[gr*W_+gc];
            s_in[i] = v;
        }
        if (tid < 72){
            int o = tid/9, kk = tid%9;
            int oc = ocg*8+o;
            s_w[kk*8+o] = (oc<Cout) ? wgt[(oc*Cin+ic)*9 + kk] : 0.f;
        }
        __syncthreads();
        #pragma unroll
        for (int dr=0;dr<3;dr++){
            #pragma unroll
            for (int dc=0;dc<3;dc++){
                int kk = dr*3+dc;
                ull v0 = pack2s(s_in[(ly   +dr)*34 + lx+dc]);
                ull v1 = pack2s(s_in[(ly+ 8+dr)*34 + lx+dc]);
                ull v2 = pack2s(s_in[(ly+16+dr)*34 + lx+dc]);
                ull v3 = pack2s(s_in[(ly+24+dr)*34 + lx+dc]);
                const ull* wrow = (const ull*)&s_w[kk*8];
                #pragma unroll
                for (int op=0;op<4;op++){
                    ull w2 = wrow[op];
                    ffma2(acc[0][op], v0, w2);
                    ffma2(acc[1][op], v1, w2);
                    ffma2(acc[2][op], v2, w2);
                    ffma2(acc[3][op], v3, w2);
                }
            }
        }
        __syncthreads();
    }

    #pragma unroll
    for (int op=0;op<4;op++){
        #pragma unroll
        for (int h=0;h<2;h++){
            int o = op*2+h;
            int oc = ocg*8+o;
            if (oc < Cout){
                float bv = bias[oc];
                #pragma unroll
                for (int p=0;p<4;p++){
                    float a0,a1; unpack2(a0,a1,acc[p][op]);
                    float r = (h ? a1 : a0) + bv;
                    if (relu) r = fmaxf(r, 0.f);
                    out[((size_t)(b*Cout+oc)*H_ + (y0+ly+p*8))*W_ + x0+lx] = r;
                }
            }
        }
    }
}

// ---------------- patches ----------------
__global__ void patches_kernel()
{
    int bn = blockIdx.x;
    int b = bn / N_, n = bn % N_;
    int n1 = n / N1_, n2 = n % N1_;
    int r0 = n1*S_, c0 = n2*S_;
    int tid = threadIdx.x;

    float loc = 0.f;
    for (int d=tid; d<D_; d+=128){
        int c = d/100, rem = d%100, p1 = rem/10, p2 = rem%10;
        float v = g_xe[((b*E_+c)*H_ + r0+p1)*W_ + c0+p2];
        g_pe[(size_t)bn*D_ + d] = v;
        loc += v*v;
    }
    float lv = 0.f;
    if (tid < 100){
        int p1 = tid/10, p2 = tid%10;
        lv = g_ltmap[(b*H_ + r0+p1)*W_ + c0+p2];
    }
    __shared__ float r1s[4], r2s[4];
    int lane = tid & 31, wid = tid >> 5;
    #pragma unroll
    for (int off=16; off; off>>=1){
        loc += __shfl_xor_sync(0xffffffffu, loc, off);
        lv  += __shfl_xor_sync(0xffffffffu, lv,  off);
    }
    if (lane==0){ r1s[wid]=loc; r2s[wid]=lv; }
    __syncthreads();
    if (tid==0){
        g_sq[bn]  = r1s[0]+r1s[1]+r1s[2]+r1s[3];
        g_ltm[bn] = (r2s[0]+r2s[1]+r2s[2]+r2s[3]) * (1.f/100.f);
    }
}

// ------- nnblock -------
__global__ void __launch_bounds__(256) nnblock_kernel(const float* __restrict__ x)
{
    extern __shared__ float sm[];
    float* s_xf = sm;
    float* s_q  = sm + 12800;
    __shared__ __align__(8) float s_wk[M_][8];
    __shared__ float s_logit[M_];
    __shared__ int   s_cand[M_];
    __shared__ int   s_off[M_];

    int bn = blockIdx.x;
    int b = bn / N_, n = bn % N_;
    int q1 = n / N1_, q2 = n % N1_;
    int tid = threadIdx.x, lane = tid & 31, wid = tid >> 5;

    int c1lo = max(q1-3,0), c1hi = min(q1+3, N1_-1);
    int c2lo = max(q2-3,0), c2hi = min(q2+3, N1_-1);
    int rows = (c1hi-c1lo)*S_ + P_;
    int cols = (c2hi-c2lo)*S_ + P_;
    int r0 = c1lo*S_, c0 = c2lo*S_;

    if (tid < M_){
        int i = tid/7, j = tid%7;
        int c1 = min(max(q1+i-3,0), N1_-1);
        int c2 = min(max(q2+j-3,0), N1_-1);
        s_cand[tid] = c1*N1_ + c2;
        s_off[tid]  = ((c1-c1lo)*S_)*40 + (c2-c2lo)*S_;
    }
    if (tid < 200)
        ((float4*)s_q)[tid] = ((const float4*)(g_pe + (size_t)bn*D_))[tid];

    #pragma unroll
    for (int c=0;c<CIN_;c++){
        const float* src = x + ((size_t)(b*CIN_+c)*H_ + r0)*W_ + c0;
        for (int r=wid; r<rows; r+=8)
            for (int cc=lane; cc<cols; cc+=32)
                s_xf[c*1600 + r*40 + cc] = src[r*W_ + cc];
    }
    __syncthreads();

    float sq_q  = g_sq[bn];
    float scale = expf(-g_ltm[bn]);

    const float4* sq4 = (const float4*)s_q;
    for (int m=wid; m<M_; m+=8){
        int cand = s_cand[m];
        const float4* pc = (const float4*)(g_pe + (size_t)(b*N_+cand)*D_);
        float s0=0.f, s1=0.f, s2=0.f, s3=0.f;
        #pragma unroll
        for (int j=0;j<6;j++){
            float4 a = pc[lane + j*32];
            float4 q = sq4[lane + j*32];
            s0 = fmaf(a.x,q.x,s0); s1 = fmaf(a.y,q.y,s1);
            s2 = fmaf(a.z,q.z,s2); s3 = fmaf(a.w,q.w,s3);
        }
        if (lane < 8){
            float4 a = pc[192+lane];
            float4 q = sq4[192+lane];
            s0 = fmaf(a.x,q.x,s0); s1 = fmaf(a.y,q.y,s1);
            s2 = fmaf(a.z,q.z,s2); s3 = fmaf(a.w,q.w,s3);
        }
        float s = (s0+s1)+(s2+s3);
        #pragma unroll
        for (int off=16; off; off>>=1) s += __shfl_xor_sync(0xffffffffu, s, off);
        if (lane==0){
            float Dv = -(sq_q + g_sq[b*N_+cand] - 2.f*s);
            s_logit[m] = (cand==n) ? -1e9f : Dv*scale;
        }
    }
    __syncthreads();

    if (tid < 32){
        float a = s_logit[tid];
        bool hasb = (tid+32) < M_;
        float bvl = hasb ? s_logit[tid+32] : -INFINITY;
        #pragma unroll
        for (int k=0;k<K_;k++){
            float mx = fmaxf(a, bvl);
            #pragma unroll
            for (int off=16; off; off>>=1) mx = fmaxf(mx, __shfl_xor_sync(0xffffffffu, mx, off));
            float ea = expf(a - mx);
            float eb = hasb ? expf(bvl - mx) : 0.f;
            float ssum = ea + eb;
            #pragma unroll
            for (int off=16; off; off>>=1) ssum += __shfl_xor_sync(0xffffffffu, ssum, off);
            float inv = 1.f/ssum;
            float wa = ea*inv, wb = eb*inv;
            s_wk[tid][k] = wa;
            if (hasb) s_wk[tid+32][k] = wb;
            a   += log1pf(-fminf(wa, 1.f-1e-6f));
            bvl += log1pf(-fminf(wb, 1.f-1e-6f));
        }
    }
    __syncthreads();

    int baseidx[4]; bool act[4];
    #pragma unroll
    for (int j=0;j<4;j++){
        int d = tid + 256*j;
        act[j] = (d < D_);
        int dd = act[j] ? d : 0;
        int c = dd/100, rem = dd%100, p1 = rem/10, p2 = rem%10;
        baseidx[j] = c*1600 + p1*40 + p2;
    }
    ull a01[4], a23[4], a45[4];
    float a6[4];
    #pragma unroll
    for (int j=0;j<4;j++){ a01[j]=0ull; a23[j]=0ull; a45[j]=0ull; a6[j]=0.f; }

    for (int m=0;m<M_;m++){
        int o = s_off[m];
        const ull* wr = (const ull*)&s_wk[m][0];
        ull w01 = wr[0], w23 = wr[1], w45 = wr[2];
        float w6 = s_wk[m][6];
        #pragma unroll
        for (int j=0;j<4;j++){
            float v = s_xf[baseidx[j]+o];
            ull vv = pack2s(v);
            ffma2(a01[j], vv, w01);
            ffma2(a23[j], vv, w23);
            ffma2(a45[j], vv, w45);
            a6[j] = fmaf(w6, v, a6[j]);
        }
    }
    #pragma unroll
    for (int j=0;j<4;j++){
        if (!act[j]) continue;
        int d = tid + 256*j;
        float o0,o1,o2,o3,o4,o5;
        unpack2(o0,o1,a01[j]); unpack2(o2,o3,a23[j]); unpack2(o4,o5,a45[j]);
        float vals[7] = {o0,o1,o2,o3,o4,o5,a6[j]};
        #pragma unroll
        for (int k=0;k<K_;k++)
            g_nb[((size_t)(k*B_+b)*N_ + n)*D_ + d] = vals[k];
    }
}

// ---------------- fold ----------------
__global__ void fold_kernel(const float* __restrict__ x, float* __restrict__ out)
{
    int idx = blockIdx.x*blockDim.x + threadIdx.x;
    const int total = B_*(K_+1)*CIN_*H_*W_;
    if (idx >= total) return;
    int w  = idx % W_;
    int r  = (idx / W_) % H_;
    int ch = (idx / (H_*W_)) % ((K_+1)*CIN_);
    int b  = idx / (H_*W_*(K_+1)*CIN_);

    if (ch < CIN_){
        out[idx] = x[((b*CIN_+ch)*H_+r)*W_+w];
        return;
    }
    int k = (ch - CIN_) / CIN_;
    int c = (ch - CIN_) % CIN_;

    int n1lo = (r >= P_-1) ? (r-(P_-1)+S_-1)/S_ : 0;
    int n1hi = min(N1_-1, r/S_);
    int n2lo = (w >= P_-1) ? (w-(P_-1)+S_-1)/S_ : 0;
    int n2hi = min(N1_-1, w/S_);

    float sum = 0.f; int cnt = 0;
    for (int n1=n1lo; n1<=n1hi; n1++){
        int p1 = r - n1*S_;
        for (int n2=n2lo; n2<=n2hi; n2++){
            int p2 = w - n2*S_;
            sum += g_nb[((size_t)(k*B_+b)*N_ + n1*N1_+n2)*D_ + c*100 + p1*10 + p2];
            cnt++;
        }
    }
    out[idx] = (cnt > 0) ? sum/(float)cnt : 0.f;
}

// ---------------- launch ----------------
extern "C" void kernel_launch(void* const* d_in, const int* in_sizes, int n_in,
                              void* d_out, int out_size)
{
    const float* x   = (const float*)d_in[0];
    const float* w1e = (const float*)d_in[1];
    const float* b1e = (const float*)d_in[2];
    const float* w2e = (const float*)d_in[3];
    const float* b2e = (const float*)d_in[4];
    const float* w3e = (const float*)d_in[5];
    const float* b3e = (const float*)d_in[6];
    const float* w1t = (const float*)d_in[7];
    const float* b1t = (const float*)d_in[8];
    const float* w2t = (const float*)d_in[9];
    const float* b2t = (const float*)d_in[10];
    const float* w3t = (const float*)d_in[11];
    const float* b3t = (const float*)d_in[12];

    float *t1e, *t1t, *t2e, *t2t, *xe, *ltmap;
    cudaGetSymbolAddress((void**)&t1e,   g_t1e);
    cudaGetSymbolAddress((void**)&t1t,   g_t1t);
    cudaGetSymbolAddress((void**)&t2e,   g_t2e);
    cudaGetSymbolAddress((void**)&t2t,   g_t2t);
    cudaGetSymbolAddress((void**)&xe,    g_xe);
    cudaGetSymbolAddress((void**)&ltmap, g_ltmap);

    static int attr_done = 0;
    if (!attr_done){
        cudaFuncSetAttribute(nnblock_kernel,
                             cudaFuncAttributeMaxDynamicSharedMemorySize, 56*1024);
        cudaFuncSetAttribute(conv2_mma,
                             cudaFuncAttributeMaxDynamicSharedMemorySize, CSM2_TOT);
        attr_done = 1;
    }

    conv1_fused<<<dim3(49,8,B_), 256>>>(x, w1e, b1e, t1e, w1t, b1t, t1t);
    wprep_kernel<<<18, 256>>>(w2e, w2t);
    nhwc_convert<<<dim3(4,226,8), 256>>>(t1e, t1t);
    conv2_mma<<<dim3(196,2,2), 256, CSM2_TOT>>>(b2e, b2t);
    conv3x3_dual<<<dim3(49,2,B_), 256>>>(t2e, w3e, b3e, xe,    E_,
                                         t2t, w3t, b3t, ltmap, 1, F_, 0, 1);

    patches_kernel<<<B_*N_, 128>>>();
    nnblock_kernel<<<B_*N_, 256, (12800+800)*sizeof(float)>>>(x);

    const int total = B_*(K_+1)*CIN_*H_*W_;
    fold_kernel<<<(total+255)/256, 256>>>(x, (float*)d_out);
}